// round 4
// baseline (speedup 1.0000x reference)
#include <cuda_runtime.h>
#include <math.h>

#define S_LEN  2048
#define E_DIM  1024
#define H_NUM  16
#define D_HEAD 64
#define B_NUM  2
#define M_TOT  (B_NUM * S_LEN)   // 4096

// ---------------- device scratch ----------------
__device__ float g_Q[(size_t)M_TOT * E_DIM];
__device__ float g_K[(size_t)M_TOT * E_DIM];
__device__ float g_V[(size_t)M_TOT * E_DIM];
__device__ float g_X[(size_t)M_TOT * E_DIM];     // tf32-rounded x
__device__ float g_Wq[(size_t)E_DIM * E_DIM];    // tf32-rounded weights
__device__ float g_Wk[(size_t)E_DIM * E_DIM];
__device__ float g_Wv[(size_t)E_DIM * E_DIM];

// ---------------- helpers ----------------
__device__ __forceinline__ unsigned f2tf(float f) {
    unsigned u;
    asm("cvt.rna.tf32.f32 %0, %1;" : "=r"(u) : "f"(f));
    return u;
}
__device__ __forceinline__ float f2tff(float f) { return __uint_as_float(f2tf(f)); }

__device__ __forceinline__ void mma_tf32(float c[4],
                                         unsigned a0, unsigned a1, unsigned a2, unsigned a3,
                                         unsigned b0, unsigned b1) {
    asm volatile(
        "mma.sync.aligned.m16n8k8.row.col.f32.tf32.tf32.f32 "
        "{%0,%1,%2,%3}, {%4,%5,%6,%7}, {%8,%9}, {%0,%1,%2,%3};"
        : "+f"(c[0]), "+f"(c[1]), "+f"(c[2]), "+f"(c[3])
        : "r"(a0), "r"(a1), "r"(a2), "r"(a3), "r"(b0), "r"(b1));
}

__device__ __forceinline__ void cp16(void* smem_dst, const void* gmem_src) {
    unsigned s = (unsigned)__cvta_generic_to_shared(smem_dst);
    asm volatile("cp.async.cg.shared.global [%0], [%1], 16;" :: "r"(s), "l"(gmem_src));
}
#define CP_COMMIT() asm volatile("cp.async.commit_group;")
#define CP_WAIT0()  asm volatile("cp.async.wait_group 0;")

// ---------------------------------------------------------------------------
// Kernel 0: elementwise tf32 rounding (RNA) prepass.
// ---------------------------------------------------------------------------
__global__ void round_k(const float* __restrict__ src, float* __restrict__ dst, int n4)
{
    int i = blockIdx.x * blockDim.x + threadIdx.x;
    if (i >= n4) return;
    float4 v = ((const float4*)src)[i];
    v.x = f2tff(v.x); v.y = f2tff(v.y); v.z = f2tff(v.z); v.w = f2tff(v.w);
    ((float4*)dst)[i] = v;
}

// ---------------------------------------------------------------------------
// Kernel 1: C = x @ W^T via m16n8k8 tf32 MMA. Tile 128x128, BK=32.
// Inputs pre-rounded => mainloop is pure LDS+MMA. For z<2 (Q,K) the epilogue
// performs the per-head (64-col) L2 norm in-register (+ g fold for Q) and
// writes tf32-rounded results; for z==2 (V) writes tf32-rounded values.
// Smem stride 36 => fragment LDS addresses are (4r+k) mod 32: conflict-free.
// ---------------------------------------------------------------------------
#define AS_SZ (128 * 36)

__global__ __launch_bounds__(256, 2) void qkv_gemm(const float* __restrict__ gptr)
{
    extern __shared__ float sm[];
    float* As[2] = { sm,            sm + AS_SZ };
    float* Bs[2] = { sm + 2*AS_SZ,  sm + 3*AS_SZ };

    const int z  = blockIdx.z;
    const float* W = (z == 0) ? g_Wq : (z == 1) ? g_Wk : g_Wv;
    float*       C = (z == 0) ? g_Q  : (z == 1) ? g_K  : g_V;

    const int m0   = blockIdx.y * 128;
    const int n0   = blockIdx.x * 128;
    const int t    = threadIdx.x;
    const int warp = t >> 5;
    const int lane = t & 31;
    const int wm   = warp >> 2;      // 0..1
    const int wn   = warp & 3;       // 0..3
    const int lr   = lane >> 2;      // 0..7
    const int lc   = lane & 3;       // 0..3

    float acc[4][4][4];
#pragma unroll
    for (int i = 0; i < 4; i++)
#pragma unroll
        for (int j = 0; j < 4; j++)
#pragma unroll
            for (int r = 0; r < 4; r++) acc[i][j][r] = 0.0f;

    auto prefetch = [&](int ks, int buf) {
        const int k0 = ks * 32;
#pragma unroll
        for (int i = 0; i < 4; i++) {
            int s   = t + i * 256;     // 0..1023
            int row = s >> 3;          // 0..127
            int c4  = s & 7;           // 0..7
            cp16(&As[buf][row * 36 + c4 * 4], &g_X[(size_t)(m0 + row) * E_DIM + k0 + c4 * 4]);
            cp16(&Bs[buf][row * 36 + c4 * 4], &W  [(size_t)(n0 + row) * E_DIM + k0 + c4 * 4]);
        }
    };

    prefetch(0, 0); CP_COMMIT();
    int buf = 0;

    for (int ks = 0; ks < 32; ks++) {
        CP_WAIT0();
        __syncthreads();                 // data ready AND everyone done with buf^1
        if (ks + 1 < 32) { prefetch(ks + 1, buf ^ 1); CP_COMMIT(); }

#pragma unroll
        for (int kk = 0; kk < 4; kk++) {
            const int kb = kk * 8;
            unsigned af[4][4];
#pragma unroll
            for (int mi = 0; mi < 4; mi++) {
                int rb = wm * 64 + mi * 16 + lr;
                af[mi][0] = __float_as_uint(As[buf][rb       * 36 + kb + lc]);
                af[mi][1] = __float_as_uint(As[buf][(rb + 8) * 36 + kb + lc]);
                af[mi][2] = __float_as_uint(As[buf][rb       * 36 + kb + lc + 4]);
                af[mi][3] = __float_as_uint(As[buf][(rb + 8) * 36 + kb + lc + 4]);
            }
            unsigned bf[4][2];
#pragma unroll
            for (int ni = 0; ni < 4; ni++) {
                int nb = wn * 32 + ni * 8 + lr;
                bf[ni][0] = __float_as_uint(Bs[buf][nb * 36 + kb + lc]);
                bf[ni][1] = __float_as_uint(Bs[buf][nb * 36 + kb + lc + 4]);
            }
#pragma unroll
            for (int mi = 0; mi < 4; mi++)
#pragma unroll
                for (int ni = 0; ni < 4; ni++)
                    mma_tf32(acc[mi][ni], af[mi][0], af[mi][1], af[mi][2], af[mi][3],
                             bf[ni][0], bf[ni][1]);
        }
        buf ^= 1;
    }

    // ---- epilogue ----
    float scale[4][2];   // per (mi, row-half) multiplier
    if (z < 2) {
        const float g = (z == 0) ? gptr[0] : 1.0f;
        // partial sum of squares over this thread's 8 cols per row
        float ss[4][2];
#pragma unroll
        for (int mi = 0; mi < 4; mi++) {
            float s0 = 0.0f, s1 = 0.0f;
#pragma unroll
            for (int ni = 0; ni < 4; ni++) {
                s0 += acc[mi][ni][0] * acc[mi][ni][0] + acc[mi][ni][1] * acc[mi][ni][1];
                s1 += acc[mi][ni][2] * acc[mi][ni][2] + acc[mi][ni][3] * acc[mi][ni][3];
            }
            ss[mi][0] = s0; ss[mi][1] = s1;
        }
        // reduce over lc (lanes differing in low 2 bits)
#pragma unroll
        for (int mi = 0; mi < 4; mi++)
#pragma unroll
            for (int h2 = 0; h2 < 2; h2++) {
                ss[mi][h2] += __shfl_xor_sync(0xffffffffu, ss[mi][h2], 1);
                ss[mi][h2] += __shfl_xor_sync(0xffffffffu, ss[mi][h2], 2);
            }
        // exchange with partner warp (wn ^ 1 shares the same 64-col head)
        __syncthreads();                     // mainloop fully done; safe to reuse sm
        float* red = sm;                     // 8 warps * 4 mi * 2 half * 8 lr = 512 floats
        if (lc == 0) {
#pragma unroll
            for (int mi = 0; mi < 4; mi++) {
                red[((warp * 4 + mi) * 2 + 0) * 8 + lr] = ss[mi][0];
                red[((warp * 4 + mi) * 2 + 1) * 8 + lr] = ss[mi][1];
            }
        }
        __syncthreads();
        const int wpartner = (wm * 4) + (wn ^ 1);
#pragma unroll
        for (int mi = 0; mi < 4; mi++) {
#pragma unroll
            for (int h2 = 0; h2 < 2; h2++) {
                float tot = ss[mi][h2] + red[((wpartner * 4 + mi) * 2 + h2) * 8 + lr];
                scale[mi][h2] = g / fmaxf(sqrtf(tot), 1e-12f);
            }
        }
    } else {
#pragma unroll
        for (int mi = 0; mi < 4; mi++) { scale[mi][0] = 1.0f; scale[mi][1] = 1.0f; }
    }

#pragma unroll
    for (int mi = 0; mi < 4; mi++) {
#pragma unroll
        for (int ni = 0; ni < 4; ni++) {
            int row = m0 + wm * 64 + mi * 16 + lr;
            int col = n0 + wn * 32 + ni * 8 + 2 * lc;
            float v0 = f2tff(acc[mi][ni][0] * scale[mi][0]);
            float v1 = f2tff(acc[mi][ni][1] * scale[mi][0]);
            float v2 = f2tff(acc[mi][ni][2] * scale[mi][1]);
            float v3 = f2tff(acc[mi][ni][3] * scale[mi][1]);
            *(float2*)&C[(size_t)row * E_DIM + col]       = make_float2(v0, v1);
            *(float2*)&C[(size_t)(row + 8) * E_DIM + col] = make_float2(v2, v3);
        }
    }
}

// ---------------------------------------------------------------------------
// Kernel 2: flash attention, tf32 MMA. Br=128, Bc=64, D=64.
// Q fragments cached in registers; P staging aliases the Q smem tile.
// |score| <= |g| => fixed max M0, no rescaling. Single sync per k-tile.
// ---------------------------------------------------------------------------
#define QS_SZ (128 * 68)
#define KS_SZ (64 * 68)
#define VS_SZ (64 * 72)

__global__ __launch_bounds__(256, 2) void attn_kernel(float* __restrict__ out,
                                                      const float* __restrict__ gptr)
{
    extern __shared__ float sm[];
    float* Qs    = sm;                 // 128*68, reused as Ps after Q->regs
    float* Ps    = sm;
    float* Ks[2] = { Qs + QS_SZ,        Qs + QS_SZ + KS_SZ };
    float* Vs[2] = { Ks[1] + KS_SZ,     Ks[1] + KS_SZ + VS_SZ };

    const int b    = blockIdx.z;
    const int h    = blockIdx.y;
    const int q0   = blockIdx.x * 128;
    const int t    = threadIdx.x;
    const int warp = t >> 5;
    const int lane = t & 31;
    const int lr   = lane >> 2;   // 0..7
    const int lc   = lane & 3;    // 0..3
    const int w16  = warp * 16;

    const float M0 = fabsf(gptr[0]);

    const float* Qg = g_Q + ((size_t)b * S_LEN + q0) * E_DIM + h * D_HEAD;
    const float* Kg = g_K + (size_t)b * S_LEN * E_DIM + h * D_HEAD;
    const float* Vg = g_V + (size_t)b * S_LEN * E_DIM + h * D_HEAD;

    auto prefetch = [&](int kt, int bufi) {
#pragma unroll
        for (int i = 0; i < 4; i++) {
            int s  = t + i * 256;
            int r  = s >> 4;
            int c4 = s & 15;
            cp16(&Ks[bufi][r * 68 + c4 * 4], &Kg[(size_t)(kt * 64 + r) * E_DIM + c4 * 4]);
            cp16(&Vs[bufi][r * 72 + c4 * 4], &Vg[(size_t)(kt * 64 + r) * E_DIM + c4 * 4]);
        }
    };
    prefetch(0, 0); CP_COMMIT();

    // stage Q tile once, pull fragments into registers
#pragma unroll
    for (int i = 0; i < 8; i++) {
        int s  = t + i * 256;
        int r  = s >> 4;
        int c4 = s & 15;
        float4 v = *(const float4*)&Qg[(size_t)r * E_DIM + c4 * 4];
        *(float4*)&Qs[r * 68 + c4 * 4] = v;
    }
    __syncthreads();

    unsigned qf[8][4];
#pragma unroll
    for (int kk = 0; kk < 8; kk++) {
        const int kb = kk * 8;
        int rb = w16 + lr;
        qf[kk][0] = __float_as_uint(Qs[rb       * 68 + kb + lc]);
        qf[kk][1] = __float_as_uint(Qs[(rb + 8) * 68 + kb + lc]);
        qf[kk][2] = __float_as_uint(Qs[rb       * 68 + kb + lc + 4]);
        qf[kk][3] = __float_as_uint(Qs[(rb + 8) * 68 + kb + lc + 4]);
    }
    // Ps rows [w16, w16+16) are warp-private => aliasing Qs is safe.

    float oc[8][4];
#pragma unroll
    for (int ni = 0; ni < 8; ni++)
#pragma unroll
        for (int r = 0; r < 4; r++) oc[ni][r] = 0.0f;
    float l0 = 0.0f, l1 = 0.0f;

    int buf = 0;
    for (int kt = 0; kt < S_LEN / 64; kt++) {
        CP_WAIT0();
        __syncthreads();               // data ready AND all warps done with buf^1
        if (kt + 1 < S_LEN / 64) { prefetch(kt + 1, buf ^ 1); CP_COMMIT(); }

        // ---- S = Q K^T ----
        float sv[8][4];
#pragma unroll
        for (int ni = 0; ni < 8; ni++)
#pragma unroll
            for (int r = 0; r < 4; r++) sv[ni][r] = 0.0f;

#pragma unroll
        for (int kk = 0; kk < 8; kk++) {
            const int kb = kk * 8;
#pragma unroll
            for (int ni = 0; ni < 8; ni++) {
                int nb = ni * 8 + lr;
                unsigned b0 = __float_as_uint(Ks[buf][nb * 68 + kb + lc]);
                unsigned b1 = __float_as_uint(Ks[buf][nb * 68 + kb + lc + 4]);
                mma_tf32(sv[ni], qf[kk][0], qf[kk][1], qf[kk][2], qf[kk][3], b0, b1);
            }
        }

        // ---- P = exp(S - M0), rounded; sums use the SAME rounded values ----
        __syncwarp();
#pragma unroll
        for (int ni = 0; ni < 8; ni++) {
            float p00 = f2tff(__expf(sv[ni][0] - M0));
            float p01 = f2tff(__expf(sv[ni][1] - M0));
            float p10 = f2tff(__expf(sv[ni][2] - M0));
            float p11 = f2tff(__expf(sv[ni][3] - M0));
            l0 += p00 + p01;
            l1 += p10 + p11;
            int col = ni * 8 + 2 * lc;
            *(float2*)&Ps[(w16 + lr)     * 68 + col] = make_float2(p00, p01);
            *(float2*)&Ps[(w16 + lr + 8) * 68 + col] = make_float2(p10, p11);
        }
        __syncwarp();

        // ---- O += P @ V ----
#pragma unroll
        for (int kk = 0; kk < 8; kk++) {
            const int kb = kk * 8;
            int rb = w16 + lr;
            unsigned a0 = __float_as_uint(Ps[rb       * 68 + kb + lc]);
            unsigned a1 = __float_as_uint(Ps[(rb + 8) * 68 + kb + lc]);
            unsigned a2 = __float_as_uint(Ps[rb       * 68 + kb + lc + 4]);
            unsigned a3 = __float_as_uint(Ps[(rb + 8) * 68 + kb + lc + 4]);
#pragma unroll
            for (int ni = 0; ni < 8; ni++) {
                unsigned b0 = __float_as_uint(Vs[buf][(kb + lc)     * 72 + ni * 8 + lr]);
                unsigned b1 = __float_as_uint(Vs[buf][(kb + lc + 4) * 72 + ni * 8 + lr]);
                mma_tf32(oc[ni], a0, a1, a2, a3, b0, b1);
            }
        }

        buf ^= 1;
    }

    // ---- epilogue ----
    l0 += __shfl_xor_sync(0xffffffffu, l0, 1);
    l0 += __shfl_xor_sync(0xffffffffu, l0, 2);
    l1 += __shfl_xor_sync(0xffffffffu, l1, 1);
    l1 += __shfl_xor_sync(0xffffffffu, l1, 2);
    float inv0 = 1.0f / l0;
    float inv1 = 1.0f / l1;

    int ra = q0 + w16 + lr;
#pragma unroll
    for (int ni = 0; ni < 8; ni++) {
        int col = h * D_HEAD + ni * 8 + 2 * lc;
        *(float2*)&out[((size_t)b * S_LEN + ra) * E_DIM + col] =
            make_float2(oc[ni][0] * inv0, oc[ni][1] * inv0);
        *(float2*)&out[((size_t)b * S_LEN + ra + 8) * E_DIM + col] =
            make_float2(oc[ni][2] * inv1, oc[ni][3] * inv1);
    }
}

// ---------------------------------------------------------------------------
extern "C" void kernel_launch(void* const* d_in, const int* in_sizes, int n_in,
                              void* d_out, int out_size)
{
    const float* x  = (const float*)d_in[0];
    const float* Wq = (const float*)d_in[1];
    const float* Wk = (const float*)d_in[2];
    const float* Wv = (const float*)d_in[3];
    const float* g  = (const float*)d_in[4];
    float* out = (float*)d_out;

    float* gX;  cudaGetSymbolAddress((void**)&gX,  g_X);
    float* gWq; cudaGetSymbolAddress((void**)&gWq, g_Wq);
    float* gWk; cudaGetSymbolAddress((void**)&gWk, g_Wk);
    float* gWv; cudaGetSymbolAddress((void**)&gWv, g_Wv);

    // 0) tf32-round inputs (RNA) so GEMM mainloops are LDS+MMA only
    round_k<<<(M_TOT * E_DIM / 4 + 255) / 256, 256>>>(x,  gX,  M_TOT * E_DIM / 4);
    round_k<<<(E_DIM * E_DIM / 4 + 255) / 256, 256>>>(Wq, gWq, E_DIM * E_DIM / 4);
    round_k<<<(E_DIM * E_DIM / 4 + 255) / 256, 256>>>(Wk, gWk, E_DIM * E_DIM / 4);
    round_k<<<(E_DIM * E_DIM / 4 + 255) / 256, 256>>>(Wv, gWv, E_DIM * E_DIM / 4);

    // 1) QKV projections + fused per-head L2 norm (g folded into Q)
    {
        size_t smem = (size_t)4 * AS_SZ * sizeof(float);   // 73728
        cudaFuncSetAttribute(qkv_gemm, cudaFuncAttributeMaxDynamicSharedMemorySize,
                             (int)smem);
        dim3 grid(E_DIM / 128, M_TOT / 128, 3);
        qkv_gemm<<<grid, 256, smem>>>(g);
    }

    // 2) Flash attention (tf32 tensor core, 2 CTAs/SM)
    {
        size_t smem = (size_t)(QS_SZ + 2 * KS_SZ + 2 * VS_SZ) * sizeof(float); // 106496
        cudaFuncSetAttribute(attn_kernel, cudaFuncAttributeMaxDynamicSharedMemorySize,
                             (int)smem);
        dim3 agrid(S_LEN / 128, H_NUM, B_NUM);
        attn_kernel<<<agrid, 256, smem>>>(out, g);
    }
}

// round 6
// speedup vs baseline: 1.5561x; 1.5561x over previous
#include <cuda_runtime.h>
#include <math.h>

#define S_LEN  2048
#define E_DIM  1024
#define H_NUM  16
#define D_HEAD 64
#define B_NUM  2
#define M_TOT  (B_NUM * S_LEN)   // 4096

// ---------------- device scratch ----------------
__device__ float g_Q[(size_t)M_TOT * E_DIM];
__device__ float g_K[(size_t)M_TOT * E_DIM];
__device__ float g_V[(size_t)M_TOT * E_DIM];
__device__ float g_X[(size_t)M_TOT * E_DIM];     // tf32-rounded x
__device__ float g_Wq[(size_t)E_DIM * E_DIM];    // tf32-rounded weights
__device__ float g_Wk[(size_t)E_DIM * E_DIM];
__device__ float g_Wv[(size_t)E_DIM * E_DIM];

// ---------------- helpers ----------------
__device__ __forceinline__ unsigned f2tf(float f) {
    unsigned u;
    asm("cvt.rna.tf32.f32 %0, %1;" : "=r"(u) : "f"(f));
    return u;
}
__device__ __forceinline__ float f2tff(float f) { return __uint_as_float(f2tf(f)); }

__device__ __forceinline__ void mma_tf32(float c[4],
                                         unsigned a0, unsigned a1, unsigned a2, unsigned a3,
                                         unsigned b0, unsigned b1) {
    asm volatile(
        "mma.sync.aligned.m16n8k8.row.col.f32.tf32.tf32.f32 "
        "{%0,%1,%2,%3}, {%4,%5,%6,%7}, {%8,%9}, {%0,%1,%2,%3};"
        : "+f"(c[0]), "+f"(c[1]), "+f"(c[2]), "+f"(c[3])
        : "r"(a0), "r"(a1), "r"(a2), "r"(a3), "r"(b0), "r"(b1));
}

__device__ __forceinline__ void cp16(void* smem_dst, const void* gmem_src) {
    unsigned s = (unsigned)__cvta_generic_to_shared(smem_dst);
    asm volatile("cp.async.cg.shared.global [%0], [%1], 16;" :: "r"(s), "l"(gmem_src));
}
#define CP_COMMIT() asm volatile("cp.async.commit_group;")
#define CP_WAIT0()  asm volatile("cp.async.wait_group 0;")

// ---------------------------------------------------------------------------
// Kernel 0: elementwise tf32 rounding (RNA) prepass.
// ---------------------------------------------------------------------------
__global__ void round_k(const float* __restrict__ src, float* __restrict__ dst, int n4)
{
    int i = blockIdx.x * blockDim.x + threadIdx.x;
    if (i >= n4) return;
    float4 v = ((const float4*)src)[i];
    v.x = f2tff(v.x); v.y = f2tff(v.y); v.z = f2tff(v.z); v.w = f2tff(v.w);
    ((float4*)dst)[i] = v;
}

// ---------------------------------------------------------------------------
// Kernel 1: C = x @ W^T via m16n8k8 tf32 MMA. Tile 128x128, BK=32.
// Inputs pre-rounded => mainloop is pure LDS+MMA. Epilogue kept trivial
// (R4 lesson: extra epilogue live ranges spill the accumulators).
// Smem stride 36 => fragment LDS addresses are (4r+k) mod 32: conflict-free.
// ---------------------------------------------------------------------------
#define AS_SZ (128 * 36)

__global__ __launch_bounds__(256, 2) void qkv_gemm()
{
    extern __shared__ float sm[];
    float* As[2] = { sm,            sm + AS_SZ };
    float* Bs[2] = { sm + 2*AS_SZ,  sm + 3*AS_SZ };

    const int z  = blockIdx.z;
    const float* W = (z == 0) ? g_Wq : (z == 1) ? g_Wk : g_Wv;
    float*       C = (z == 0) ? g_Q  : (z == 1) ? g_K  : g_V;

    const int m0   = blockIdx.y * 128;
    const int n0   = blockIdx.x * 128;
    const int t    = threadIdx.x;
    const int warp = t >> 5;
    const int lane = t & 31;
    const int wm   = warp >> 2;      // 0..1
    const int wn   = warp & 3;       // 0..3
    const int lr   = lane >> 2;      // 0..7
    const int lc   = lane & 3;       // 0..3

    float acc[4][4][4];
#pragma unroll
    for (int i = 0; i < 4; i++)
#pragma unroll
        for (int j = 0; j < 4; j++)
#pragma unroll
            for (int r = 0; r < 4; r++) acc[i][j][r] = 0.0f;

    auto prefetch = [&](int ks, int buf) {
        const int k0 = ks * 32;
#pragma unroll
        for (int i = 0; i < 4; i++) {
            int s   = t + i * 256;     // 0..1023
            int row = s >> 3;          // 0..127
            int c4  = s & 7;           // 0..7
            cp16(&As[buf][row * 36 + c4 * 4], &g_X[(size_t)(m0 + row) * E_DIM + k0 + c4 * 4]);
            cp16(&Bs[buf][row * 36 + c4 * 4], &W  [(size_t)(n0 + row) * E_DIM + k0 + c4 * 4]);
        }
    };

    prefetch(0, 0); CP_COMMIT();
    int buf = 0;

    for (int ks = 0; ks < 32; ks++) {
        CP_WAIT0();
        __syncthreads();                 // data ready AND everyone done with buf^1
        if (ks + 1 < 32) { prefetch(ks + 1, buf ^ 1); CP_COMMIT(); }

#pragma unroll
        for (int kk = 0; kk < 4; kk++) {
            const int kb = kk * 8;
            unsigned af[4][4];
#pragma unroll
            for (int mi = 0; mi < 4; mi++) {
                int rb = wm * 64 + mi * 16 + lr;
                af[mi][0] = __float_as_uint(As[buf][rb       * 36 + kb + lc]);
                af[mi][1] = __float_as_uint(As[buf][(rb + 8) * 36 + kb + lc]);
                af[mi][2] = __float_as_uint(As[buf][rb       * 36 + kb + lc + 4]);
                af[mi][3] = __float_as_uint(As[buf][(rb + 8) * 36 + kb + lc + 4]);
            }
            unsigned bf[4][2];
#pragma unroll
            for (int ni = 0; ni < 4; ni++) {
                int nb = wn * 32 + ni * 8 + lr;
                bf[ni][0] = __float_as_uint(Bs[buf][nb * 36 + kb + lc]);
                bf[ni][1] = __float_as_uint(Bs[buf][nb * 36 + kb + lc + 4]);
            }
#pragma unroll
            for (int mi = 0; mi < 4; mi++)
#pragma unroll
                for (int ni = 0; ni < 4; ni++)
                    mma_tf32(acc[mi][ni], af[mi][0], af[mi][1], af[mi][2], af[mi][3],
                             bf[ni][0], bf[ni][1]);
        }
        buf ^= 1;
    }

    // trivial epilogue; V rounded to tf32 here (Q/K rounded in norm_heads)
#pragma unroll
    for (int mi = 0; mi < 4; mi++) {
#pragma unroll
        for (int ni = 0; ni < 4; ni++) {
            int row = m0 + wm * 64 + mi * 16 + lr;
            int col = n0 + wn * 32 + ni * 8 + 2 * lc;
            float v0 = acc[mi][ni][0], v1 = acc[mi][ni][1];
            float v2 = acc[mi][ni][2], v3 = acc[mi][ni][3];
            if (z == 2) { v0 = f2tff(v0); v1 = f2tff(v1); v2 = f2tff(v2); v3 = f2tff(v3); }
            *(float2*)&C[(size_t)row * E_DIM + col]       = make_float2(v0, v1);
            *(float2*)&C[(size_t)(row + 8) * E_DIM + col] = make_float2(v2, v3);
        }
    }
}

// ---------------------------------------------------------------------------
// Kernel 2: per-head L2 norm; fold g into Q; write tf32-rounded values.
// ---------------------------------------------------------------------------
__global__ __launch_bounds__(256) void norm_heads(const float* __restrict__ gptr)
{
    int warp = (blockIdx.x * blockDim.x + threadIdx.x) >> 5;
    int lane = threadIdx.x & 31;
    const int total = M_TOT * H_NUM;
    if (warp >= total) return;

    float* buf = (blockIdx.y == 0) ? g_Q : g_K;
    float  sc  = (blockIdx.y == 0) ? *gptr : 1.0f;
    float* p   = buf + (size_t)warp * 64;

    float2 v = *(float2*)&p[lane * 2];
    float ss = v.x * v.x + v.y * v.y;
#pragma unroll
    for (int m = 16; m > 0; m >>= 1) ss += __shfl_xor_sync(0xffffffffu, ss, m);
    float inv = sc / fmaxf(sqrtf(ss), 1e-12f);
    v.x = f2tff(v.x * inv);
    v.y = f2tff(v.y * inv);
    *(float2*)&p[lane * 2] = v;
}

// ---------------------------------------------------------------------------
// Kernel 3: flash attention, tf32 MMA. Br=128, Bc=64, D=64. (R3-proven body)
// Q fragments cached in registers; P staging aliases the Q smem tile => 2 CTAs/SM.
// |score| <= |g| => fixed max M0, no rescaling.
// ---------------------------------------------------------------------------
#define QS_SZ (128 * 68)
#define KS_SZ (64 * 68)
#define VS_SZ (64 * 72)

__global__ __launch_bounds__(256, 2) void attn_kernel(float* __restrict__ out,
                                                      const float* __restrict__ gptr)
{
    extern __shared__ float sm[];
    float* Qs    = sm;                 // 128*68, reused as Ps after Q->regs
    float* Ps    = sm;
    float* Ks[2] = { Qs + QS_SZ,        Qs + QS_SZ + KS_SZ };
    float* Vs[2] = { Ks[1] + KS_SZ,     Ks[1] + KS_SZ + VS_SZ };

    const int b    = blockIdx.z;
    const int h    = blockIdx.y;
    const int q0   = blockIdx.x * 128;
    const int t    = threadIdx.x;
    const int warp = t >> 5;
    const int lane = t & 31;
    const int lr   = lane >> 2;   // 0..7
    const int lc   = lane & 3;    // 0..3
    const int w16  = warp * 16;

    const float M0 = fabsf(gptr[0]);

    const float* Qg = g_Q + ((size_t)b * S_LEN + q0) * E_DIM + h * D_HEAD;
    const float* Kg = g_K + (size_t)b * S_LEN * E_DIM + h * D_HEAD;
    const float* Vg = g_V + (size_t)b * S_LEN * E_DIM + h * D_HEAD;

    auto prefetch = [&](int kt, int bufi) {
#pragma unroll
        for (int i = 0; i < 4; i++) {
            int s  = t + i * 256;
            int r  = s >> 4;
            int c4 = s & 15;
            cp16(&Ks[bufi][r * 68 + c4 * 4], &Kg[(size_t)(kt * 64 + r) * E_DIM + c4 * 4]);
            cp16(&Vs[bufi][r * 72 + c4 * 4], &Vg[(size_t)(kt * 64 + r) * E_DIM + c4 * 4]);
        }
    };
    prefetch(0, 0); CP_COMMIT();

    // stage Q tile once, pull fragments into registers
#pragma unroll
    for (int i = 0; i < 8; i++) {
        int s  = t + i * 256;
        int r  = s >> 4;
        int c4 = s & 15;
        float4 v = *(const float4*)&Qg[(size_t)r * E_DIM + c4 * 4];
        *(float4*)&Qs[r * 68 + c4 * 4] = v;
    }
    __syncthreads();

    unsigned qf[8][4];
#pragma unroll
    for (int kk = 0; kk < 8; kk++) {
        const int kb = kk * 8;
        int rb = w16 + lr;
        qf[kk][0] = __float_as_uint(Qs[rb       * 68 + kb + lc]);
        qf[kk][1] = __float_as_uint(Qs[(rb + 8) * 68 + kb + lc]);
        qf[kk][2] = __float_as_uint(Qs[rb       * 68 + kb + lc + 4]);
        qf[kk][3] = __float_as_uint(Qs[(rb + 8) * 68 + kb + lc + 4]);
    }
    // Ps rows [w16, w16+16) are warp-private => aliasing Qs is safe.

    float oc[8][4];
#pragma unroll
    for (int ni = 0; ni < 8; ni++)
#pragma unroll
        for (int r = 0; r < 4; r++) oc[ni][r] = 0.0f;
    float l0 = 0.0f, l1 = 0.0f;

    int buf = 0;
    for (int kt = 0; kt < S_LEN / 64; kt++) {
        CP_WAIT0();
        __syncthreads();               // data ready AND all warps done with buf^1
        if (kt + 1 < S_LEN / 64) { prefetch(kt + 1, buf ^ 1); CP_COMMIT(); }

        // ---- S = Q K^T ----
        float sv[8][4];
#pragma unroll
        for (int ni = 0; ni < 8; ni++)
#pragma unroll
            for (int r = 0; r < 4; r++) sv[ni][r] = 0.0f;

#pragma unroll
        for (int kk = 0; kk < 8; kk++) {
            const int kb = kk * 8;
#pragma unroll
            for (int ni = 0; ni < 8; ni++) {
                int nb = ni * 8 + lr;
                unsigned b0 = __float_as_uint(Ks[buf][nb * 68 + kb + lc]);
                unsigned b1 = __float_as_uint(Ks[buf][nb * 68 + kb + lc + 4]);
                mma_tf32(sv[ni], qf[kk][0], qf[kk][1], qf[kk][2], qf[kk][3], b0, b1);
            }
        }

        // ---- P = exp(S - M0); stage rounded, sum rounded ----
        __syncwarp();
#pragma unroll
        for (int ni = 0; ni < 8; ni++) {
            float p00 = f2tff(__expf(sv[ni][0] - M0));
            float p01 = f2tff(__expf(sv[ni][1] - M0));
            float p10 = f2tff(__expf(sv[ni][2] - M0));
            float p11 = f2tff(__expf(sv[ni][3] - M0));
            l0 += p00 + p01;
            l1 += p10 + p11;
            int col = ni * 8 + 2 * lc;
            *(float2*)&Ps[(w16 + lr)     * 68 + col] = make_float2(p00, p01);
            *(float2*)&Ps[(w16 + lr + 8) * 68 + col] = make_float2(p10, p11);
        }
        __syncwarp();

        // ---- O += P @ V ----
#pragma unroll
        for (int kk = 0; kk < 8; kk++) {
            const int kb = kk * 8;
            int rb = w16 + lr;
            unsigned a0 = __float_as_uint(Ps[rb       * 68 + kb + lc]);
            unsigned a1 = __float_as_uint(Ps[(rb + 8) * 68 + kb + lc]);
            unsigned a2 = __float_as_uint(Ps[rb       * 68 + kb + lc + 4]);
            unsigned a3 = __float_as_uint(Ps[(rb + 8) * 68 + kb + lc + 4]);
#pragma unroll
            for (int ni = 0; ni < 8; ni++) {
                unsigned b0 = __float_as_uint(Vs[buf][(kb + lc)     * 72 + ni * 8 + lr]);
                unsigned b1 = __float_as_uint(Vs[buf][(kb + lc + 4) * 72 + ni * 8 + lr]);
                mma_tf32(oc[ni], a0, a1, a2, a3, b0, b1);
            }
        }

        buf ^= 1;
    }

    // ---- epilogue ----
    l0 += __shfl_xor_sync(0xffffffffu, l0, 1);
    l0 += __shfl_xor_sync(0xffffffffu, l0, 2);
    l1 += __shfl_xor_sync(0xffffffffu, l1, 1);
    l1 += __shfl_xor_sync(0xffffffffu, l1, 2);
    float inv0 = 1.0f / l0;
    float inv1 = 1.0f / l1;

    int ra = q0 + w16 + lr;
#pragma unroll
    for (int ni = 0; ni < 8; ni++) {
        int col = h * D_HEAD + ni * 8 + 2 * lc;
        *(float2*)&out[((size_t)b * S_LEN + ra) * E_DIM + col] =
            make_float2(oc[ni][0] * inv0, oc[ni][1] * inv0);
        *(float2*)&out[((size_t)b * S_LEN + ra + 8) * E_DIM + col] =
            make_float2(oc[ni][2] * inv1, oc[ni][3] * inv1);
    }
}

// ---------------------------------------------------------------------------
extern "C" void kernel_launch(void* const* d_in, const int* in_sizes, int n_in,
                              void* d_out, int out_size)
{
    const float* x  = (const float*)d_in[0];
    const float* Wq = (const float*)d_in[1];
    const float* Wk = (const float*)d_in[2];
    const float* Wv = (const float*)d_in[3];
    const float* g  = (const float*)d_in[4];
    float* out = (float*)d_out;

    float* gX;  cudaGetSymbolAddress((void**)&gX,  g_X);
    float* gWq; cudaGetSymbolAddress((void**)&gWq, g_Wq);
    float* gWk; cudaGetSymbolAddress((void**)&gWk, g_Wk);
    float* gWv; cudaGetSymbolAddress((void**)&gWv, g_Wv);

    // 0) tf32-round inputs (RNA) so GEMM mainloops are LDS+MMA only
    round_k<<<(M_TOT * E_DIM / 4 + 255) / 256, 256>>>(x,  gX,  M_TOT * E_DIM / 4);
    round_k<<<(E_DIM * E_DIM / 4 + 255) / 256, 256>>>(Wq, gWq, E_DIM * E_DIM / 4);
    round_k<<<(E_DIM * E_DIM / 4 + 255) / 256, 256>>>(Wk, gWk, E_DIM * E_DIM / 4);
    round_k<<<(E_DIM * E_DIM / 4 + 255) / 256, 256>>>(Wv, gWv, E_DIM * E_DIM / 4);

    // 1) QKV projections (pure LDS+MMA mainloop, trivial epilogue)
    {
        size_t smem = (size_t)4 * AS_SZ * sizeof(float);   // 73728
        cudaFuncSetAttribute(qkv_gemm, cudaFuncAttributeMaxDynamicSharedMemorySize,
                             (int)smem);
        dim3 grid(E_DIM / 128, M_TOT / 128, 3);
        qkv_gemm<<<grid, 256, smem>>>();
    }

    // 2) L2 norm per head (g folded into Q; outputs tf32-rounded)
    {
        const int chunks = M_TOT * H_NUM;
        dim3 ngrid(chunks / 8, 2);
        norm_heads<<<ngrid, 256>>>(g);
    }

    // 3) Flash attention (tf32 tensor core, 2 CTAs/SM)
    {
        size_t smem = (size_t)(QS_SZ + 2 * KS_SZ + 2 * VS_SZ) * sizeof(float); // 106496
        cudaFuncSetAttribute(attn_kernel, cudaFuncAttributeMaxDynamicSharedMemorySize,
                             (int)smem);
        dim3 agrid(S_LEN / 128, H_NUM, B_NUM);
        attn_kernel<<<agrid, 256, smem>>>(out, g);
    }
}

// round 7
// speedup vs baseline: 1.5857x; 1.0190x over previous
#include <cuda_runtime.h>
#include <math.h>

#define S_LEN  2048
#define E_DIM  1024
#define H_NUM  16
#define D_HEAD 64
#define B_NUM  2
#define M_TOT  (B_NUM * S_LEN)   // 4096

// ---------------- device scratch ----------------
__device__ float g_Q[(size_t)M_TOT * E_DIM];
__device__ float g_K[(size_t)M_TOT * E_DIM];
__device__ float g_V[(size_t)M_TOT * E_DIM];
__device__ float g_X[(size_t)M_TOT * E_DIM];     // tf32-rounded x
__device__ float g_Wq[(size_t)E_DIM * E_DIM];    // tf32-rounded weights
__device__ float g_Wk[(size_t)E_DIM * E_DIM];
__device__ float g_Wv[(size_t)E_DIM * E_DIM];

// ---------------- helpers ----------------
__device__ __forceinline__ unsigned f2tf(float f) {
    unsigned u;
    asm("cvt.rna.tf32.f32 %0, %1;" : "=r"(u) : "f"(f));
    return u;
}
__device__ __forceinline__ float f2tff(float f) { return __uint_as_float(f2tf(f)); }

__device__ __forceinline__ void mma_tf32(float c[4],
                                         unsigned a0, unsigned a1, unsigned a2, unsigned a3,
                                         unsigned b0, unsigned b1) {
    asm volatile(
        "mma.sync.aligned.m16n8k8.row.col.f32.tf32.tf32.f32 "
        "{%0,%1,%2,%3}, {%4,%5,%6,%7}, {%8,%9}, {%0,%1,%2,%3};"
        : "+f"(c[0]), "+f"(c[1]), "+f"(c[2]), "+f"(c[3])
        : "r"(a0), "r"(a1), "r"(a2), "r"(a3), "r"(b0), "r"(b1));
}

__device__ __forceinline__ void cp16(void* smem_dst, const void* gmem_src) {
    unsigned s = (unsigned)__cvta_generic_to_shared(smem_dst);
    asm volatile("cp.async.cg.shared.global [%0], [%1], 16;" :: "r"(s), "l"(gmem_src));
}
#define CP_COMMIT() asm volatile("cp.async.commit_group;")
#define CP_WAIT0()  asm volatile("cp.async.wait_group 0;")

// ---------------------------------------------------------------------------
// Kernel 0: elementwise tf32 rounding (RNA) prepass.
// ---------------------------------------------------------------------------
__global__ void round_k(const float* __restrict__ src, float* __restrict__ dst, int n4)
{
    int i = blockIdx.x * blockDim.x + threadIdx.x;
    if (i >= n4) return;
    float4 v = ((const float4*)src)[i];
    v.x = f2tff(v.x); v.y = f2tff(v.y); v.z = f2tff(v.z); v.w = f2tff(v.w);
    ((float4*)dst)[i] = v;
}

// ---------------------------------------------------------------------------
// Kernel 1: C = x @ W^T via m16n8k8 tf32 MMA. (unchanged from R5 best)
// ---------------------------------------------------------------------------
#define AS_SZ (128 * 36)

__global__ __launch_bounds__(256, 2) void qkv_gemm()
{
    extern __shared__ float sm[];
    float* As[2] = { sm,            sm + AS_SZ };
    float* Bs[2] = { sm + 2*AS_SZ,  sm + 3*AS_SZ };

    const int z  = blockIdx.z;
    const float* W = (z == 0) ? g_Wq : (z == 1) ? g_Wk : g_Wv;
    float*       C = (z == 0) ? g_Q  : (z == 1) ? g_K  : g_V;

    const int m0   = blockIdx.y * 128;
    const int n0   = blockIdx.x * 128;
    const int t    = threadIdx.x;
    const int warp = t >> 5;
    const int lane = t & 31;
    const int wm   = warp >> 2;
    const int wn   = warp & 3;
    const int lr   = lane >> 2;
    const int lc   = lane & 3;

    float acc[4][4][4];
#pragma unroll
    for (int i = 0; i < 4; i++)
#pragma unroll
        for (int j = 0; j < 4; j++)
#pragma unroll
            for (int r = 0; r < 4; r++) acc[i][j][r] = 0.0f;

    auto prefetch = [&](int ks, int buf) {
        const int k0 = ks * 32;
#pragma unroll
        for (int i = 0; i < 4; i++) {
            int s   = t + i * 256;
            int row = s >> 3;
            int c4  = s & 7;
            cp16(&As[buf][row * 36 + c4 * 4], &g_X[(size_t)(m0 + row) * E_DIM + k0 + c4 * 4]);
            cp16(&Bs[buf][row * 36 + c4 * 4], &W  [(size_t)(n0 + row) * E_DIM + k0 + c4 * 4]);
        }
    };

    prefetch(0, 0); CP_COMMIT();
    int buf = 0;

    for (int ks = 0; ks < 32; ks++) {
        CP_WAIT0();
        __syncthreads();
        if (ks + 1 < 32) { prefetch(ks + 1, buf ^ 1); CP_COMMIT(); }

#pragma unroll
        for (int kk = 0; kk < 4; kk++) {
            const int kb = kk * 8;
            unsigned af[4][4];
#pragma unroll
            for (int mi = 0; mi < 4; mi++) {
                int rb = wm * 64 + mi * 16 + lr;
                af[mi][0] = __float_as_uint(As[buf][rb       * 36 + kb + lc]);
                af[mi][1] = __float_as_uint(As[buf][(rb + 8) * 36 + kb + lc]);
                af[mi][2] = __float_as_uint(As[buf][rb       * 36 + kb + lc + 4]);
                af[mi][3] = __float_as_uint(As[buf][(rb + 8) * 36 + kb + lc + 4]);
            }
            unsigned bf[4][2];
#pragma unroll
            for (int ni = 0; ni < 4; ni++) {
                int nb = wn * 32 + ni * 8 + lr;
                bf[ni][0] = __float_as_uint(Bs[buf][nb * 36 + kb + lc]);
                bf[ni][1] = __float_as_uint(Bs[buf][nb * 36 + kb + lc + 4]);
            }
#pragma unroll
            for (int mi = 0; mi < 4; mi++)
#pragma unroll
                for (int ni = 0; ni < 4; ni++)
                    mma_tf32(acc[mi][ni], af[mi][0], af[mi][1], af[mi][2], af[mi][3],
                             bf[ni][0], bf[ni][1]);
        }
        buf ^= 1;
    }

#pragma unroll
    for (int mi = 0; mi < 4; mi++) {
#pragma unroll
        for (int ni = 0; ni < 4; ni++) {
            int row = m0 + wm * 64 + mi * 16 + lr;
            int col = n0 + wn * 32 + ni * 8 + 2 * lc;
            float v0 = acc[mi][ni][0], v1 = acc[mi][ni][1];
            float v2 = acc[mi][ni][2], v3 = acc[mi][ni][3];
            if (z == 2) { v0 = f2tff(v0); v1 = f2tff(v1); v2 = f2tff(v2); v3 = f2tff(v3); }
            *(float2*)&C[(size_t)row * E_DIM + col]       = make_float2(v0, v1);
            *(float2*)&C[(size_t)(row + 8) * E_DIM + col] = make_float2(v2, v3);
        }
    }
}

// ---------------------------------------------------------------------------
// Kernel 2: per-head L2 norm; fold g into Q; write tf32-rounded values.
// ---------------------------------------------------------------------------
__global__ __launch_bounds__(256) void norm_heads(const float* __restrict__ gptr)
{
    int warp = (blockIdx.x * blockDim.x + threadIdx.x) >> 5;
    int lane = threadIdx.x & 31;
    const int total = M_TOT * H_NUM;
    if (warp >= total) return;

    float* buf = (blockIdx.y == 0) ? g_Q : g_K;
    float  sc  = (blockIdx.y == 0) ? *gptr : 1.0f;
    float* p   = buf + (size_t)warp * 64;

    float2 v = *(float2*)&p[lane * 2];
    float ss = v.x * v.x + v.y * v.y;
#pragma unroll
    for (int m = 16; m > 0; m >>= 1) ss += __shfl_xor_sync(0xffffffffu, ss, m);
    float inv = sc / fmaxf(sqrtf(ss), 1e-12f);
    v.x = f2tff(v.x * inv);
    v.y = f2tff(v.y * inv);
    *(float2*)&p[lane * 2] = v;
}

// ---------------------------------------------------------------------------
// Kernel 3: flash attention, tf32 MMA. Br=64, Bc=64, D=64, warp-pair split.
// 8 warps: warp = (rpair, side). Each warp: 16 rows x 32 cols. The pair
// covers 64 cols => K/V fragment loads HALVE vs all-cols-per-warp. P halves
// are exchanged through the smem stage (aliases Q tile); row sums exchanged
// once at the epilogue. |score| <= |g| => fixed max M0, no rescaling.
// ---------------------------------------------------------------------------
#define QS_SZ (64 * 68)          // Q stage, aliased by P stage
#define KS_SZ (64 * 68)
#define VS_SZ (64 * 72)
#define LRED_OFF (QS_SZ + 2 * KS_SZ + 2 * VS_SZ)
#define ATTN_SMEM ((LRED_OFF + 128) * sizeof(float))   // ~89.6 KB -> 2 CTAs/SM

__global__ __launch_bounds__(256, 2) void attn_kernel(float* __restrict__ out,
                                                      const float* __restrict__ gptr)
{
    extern __shared__ float sm[];
    float* Qs    = sm;                 // 64*68, reused as Ps after Q->regs
    float* Ps    = sm;
    float* Ks[2] = { Qs + QS_SZ,        Qs + QS_SZ + KS_SZ };
    float* Vs[2] = { Ks[1] + KS_SZ,     Ks[1] + KS_SZ + VS_SZ };
    float* lred  = sm + LRED_OFF;      // 8 warps * 16 rows

    const int b     = blockIdx.z;
    const int h     = blockIdx.y;
    const int q0    = blockIdx.x * 64;
    const int t     = threadIdx.x;
    const int warp  = t >> 5;
    const int lane  = t & 31;
    const int lr    = lane >> 2;   // 0..7
    const int lc    = lane & 3;    // 0..3
    const int rpair = warp >> 1;   // 0..3  (row block of 16)
    const int side  = warp & 1;    // 0..1  (column half of 32)
    const int r0    = rpair * 16;
    const int c0    = side * 32;

    const float M0 = fabsf(gptr[0]);

    const float* Qg = g_Q + ((size_t)b * S_LEN + q0) * E_DIM + h * D_HEAD;
    const float* Kg = g_K + (size_t)b * S_LEN * E_DIM + h * D_HEAD;
    const float* Vg = g_V + (size_t)b * S_LEN * E_DIM + h * D_HEAD;

    auto prefetch = [&](int kt, int bufi) {
#pragma unroll
        for (int i = 0; i < 4; i++) {
            int s  = t + i * 256;
            int r  = s >> 4;
            int c4 = s & 15;
            cp16(&Ks[bufi][r * 68 + c4 * 4], &Kg[(size_t)(kt * 64 + r) * E_DIM + c4 * 4]);
            cp16(&Vs[bufi][r * 72 + c4 * 4], &Vg[(size_t)(kt * 64 + r) * E_DIM + c4 * 4]);
        }
    };
    prefetch(0, 0); CP_COMMIT();

    // stage Q tile (64x64) once, pull this warp's fragments into registers
#pragma unroll
    for (int i = 0; i < 4; i++) {
        int s  = t + i * 256;
        int r  = s >> 4;
        int c4 = s & 15;
        float4 v = *(const float4*)&Qg[(size_t)r * E_DIM + c4 * 4];
        *(float4*)&Qs[r * 68 + c4 * 4] = v;
    }
    __syncthreads();

    unsigned qf[8][4];
#pragma unroll
    for (int kk = 0; kk < 8; kk++) {
        const int kb = kk * 8;
        int rb = r0 + lr;
        qf[kk][0] = __float_as_uint(Qs[rb       * 68 + kb + lc]);
        qf[kk][1] = __float_as_uint(Qs[(rb + 8) * 68 + kb + lc]);
        qf[kk][2] = __float_as_uint(Qs[rb       * 68 + kb + lc + 4]);
        qf[kk][3] = __float_as_uint(Qs[(rb + 8) * 68 + kb + lc + 4]);
    }
    // First Ps write happens after the first top-of-loop __syncthreads, so
    // every warp has extracted its Q fragments before Qs is overwritten.

    float oc[4][4];
#pragma unroll
    for (int ni = 0; ni < 4; ni++)
#pragma unroll
        for (int r = 0; r < 4; r++) oc[ni][r] = 0.0f;
    float l0 = 0.0f, l1 = 0.0f;

    int buf = 0;
    for (int kt = 0; kt < S_LEN / 64; kt++) {
        CP_WAIT0();
        __syncthreads();               // K/V ready; prev-iter Ps reads done
        if (kt + 1 < S_LEN / 64) { prefetch(kt + 1, buf ^ 1); CP_COMMIT(); }

        // ---- S = Q K^T  (rows r0..r0+15, cols c0..c0+31) ----
        float sv[4][4];
#pragma unroll
        for (int ni = 0; ni < 4; ni++)
#pragma unroll
            for (int r = 0; r < 4; r++) sv[ni][r] = 0.0f;

#pragma unroll
        for (int kk = 0; kk < 8; kk++) {
            const int kb = kk * 8;
#pragma unroll
            for (int ni = 0; ni < 4; ni++) {
                int nb = c0 + ni * 8 + lr;
                unsigned b0 = __float_as_uint(Ks[buf][nb * 68 + kb + lc]);
                unsigned b1 = __float_as_uint(Ks[buf][nb * 68 + kb + lc + 4]);
                mma_tf32(sv[ni], qf[kk][0], qf[kk][1], qf[kk][2], qf[kk][3], b0, b1);
            }
        }

        // ---- P = exp(S - M0) (rounded); stage own half, sum rounded ----
#pragma unroll
        for (int ni = 0; ni < 4; ni++) {
            float p00 = f2tff(__expf(sv[ni][0] - M0));
            float p01 = f2tff(__expf(sv[ni][1] - M0));
            float p10 = f2tff(__expf(sv[ni][2] - M0));
            float p11 = f2tff(__expf(sv[ni][3] - M0));
            l0 += p00 + p01;
            l1 += p10 + p11;
            int col = c0 + ni * 8 + 2 * lc;
            *(float2*)&Ps[(r0 + lr)     * 68 + col] = make_float2(p00, p01);
            *(float2*)&Ps[(r0 + lr + 8) * 68 + col] = make_float2(p10, p11);
        }
        __syncthreads();               // both halves of P visible

        // ---- O += P @ V  (P rows r0..+15 over ALL 64 s-cols; V cols c0..+31)
#pragma unroll
        for (int kk = 0; kk < 8; kk++) {
            const int kb = kk * 8;
            int rb = r0 + lr;
            unsigned a0 = __float_as_uint(Ps[rb       * 68 + kb + lc]);
            unsigned a1 = __float_as_uint(Ps[(rb + 8) * 68 + kb + lc]);
            unsigned a2 = __float_as_uint(Ps[rb       * 68 + kb + lc + 4]);
            unsigned a3 = __float_as_uint(Ps[(rb + 8) * 68 + kb + lc + 4]);
#pragma unroll
            for (int ni = 0; ni < 4; ni++) {
                unsigned b0 = __float_as_uint(Vs[buf][(kb + lc)     * 72 + c0 + ni * 8 + lr]);
                unsigned b1 = __float_as_uint(Vs[buf][(kb + lc + 4) * 72 + c0 + ni * 8 + lr]);
                mma_tf32(oc[ni], a0, a1, a2, a3, b0, b1);
            }
        }

        buf ^= 1;
    }

    // ---- epilogue: combine partner column-half row sums, normalize ----
    l0 += __shfl_xor_sync(0xffffffffu, l0, 1);
    l0 += __shfl_xor_sync(0xffffffffu, l0, 2);
    l1 += __shfl_xor_sync(0xffffffffu, l1, 1);
    l1 += __shfl_xor_sync(0xffffffffu, l1, 2);
    lred[warp * 16 + lr]     = l0;     // all lc lanes write same value
    lred[warp * 16 + 8 + lr] = l1;
    __syncthreads();
    const int pw = warp ^ 1;
    float inv0 = 1.0f / (l0 + lred[pw * 16 + lr]);
    float inv1 = 1.0f / (l1 + lred[pw * 16 + 8 + lr]);

    int ra = q0 + r0 + lr;
#pragma unroll
    for (int ni = 0; ni < 4; ni++) {
        int col = h * D_HEAD + c0 + ni * 8 + 2 * lc;
        *(float2*)&out[((size_t)b * S_LEN + ra) * E_DIM + col] =
            make_float2(oc[ni][0] * inv0, oc[ni][1] * inv0);
        *(float2*)&out[((size_t)b * S_LEN + ra + 8) * E_DIM + col] =
            make_float2(oc[ni][2] * inv1, oc[ni][3] * inv1);
    }
}

// ---------------------------------------------------------------------------
extern "C" void kernel_launch(void* const* d_in, const int* in_sizes, int n_in,
                              void* d_out, int out_size)
{
    const float* x  = (const float*)d_in[0];
    const float* Wq = (const float*)d_in[1];
    const float* Wk = (const float*)d_in[2];
    const float* Wv = (const float*)d_in[3];
    const float* g  = (const float*)d_in[4];
    float* out = (float*)d_out;

    float* gX;  cudaGetSymbolAddress((void**)&gX,  g_X);
    float* gWq; cudaGetSymbolAddress((void**)&gWq, g_Wq);
    float* gWk; cudaGetSymbolAddress((void**)&gWk, g_Wk);
    float* gWv; cudaGetSymbolAddress((void**)&gWv, g_Wv);

    // 0) tf32-round inputs (RNA)
    round_k<<<(M_TOT * E_DIM / 4 + 255) / 256, 256>>>(x,  gX,  M_TOT * E_DIM / 4);
    round_k<<<(E_DIM * E_DIM / 4 + 255) / 256, 256>>>(Wq, gWq, E_DIM * E_DIM / 4);
    round_k<<<(E_DIM * E_DIM / 4 + 255) / 256, 256>>>(Wk, gWk, E_DIM * E_DIM / 4);
    round_k<<<(E_DIM * E_DIM / 4 + 255) / 256, 256>>>(Wv, gWv, E_DIM * E_DIM / 4);

    // 1) QKV projections
    {
        size_t smem = (size_t)4 * AS_SZ * sizeof(float);   // 73728
        cudaFuncSetAttribute(qkv_gemm, cudaFuncAttributeMaxDynamicSharedMemorySize,
                             (int)smem);
        dim3 grid(E_DIM / 128, M_TOT / 128, 3);
        qkv_gemm<<<grid, 256, smem>>>();
    }

    // 2) L2 norm per head (g folded into Q)
    {
        const int chunks = M_TOT * H_NUM;
        dim3 ngrid(chunks / 8, 2);
        norm_heads<<<ngrid, 256>>>(g);
    }

    // 3) Flash attention (warp-pair split, 2 CTAs/SM)
    {
        cudaFuncSetAttribute(attn_kernel, cudaFuncAttributeMaxDynamicSharedMemorySize,
                             (int)ATTN_SMEM);
        dim3 agrid(S_LEN / 64, H_NUM, B_NUM);
        attn_kernel<<<agrid, 256, ATTN_SMEM>>>(out, g);
    }
}

// round 8
// speedup vs baseline: 2.6418x; 1.6660x over previous
#include <cuda_runtime.h>
#include <cuda_fp16.h>
#include <math.h>

#define S_LEN  2048
#define E_DIM  1024
#define H_NUM  16
#define D_HEAD 64
#define B_NUM  2
#define M_TOT  (B_NUM * S_LEN)   // 4096

// ---------------- device scratch ----------------
__device__ float  g_Q[(size_t)M_TOT * E_DIM];     // fp32 projections
__device__ float  g_K[(size_t)M_TOT * E_DIM];
__device__ float  g_V[(size_t)M_TOT * E_DIM];
__device__ __half g_Xh[(size_t)M_TOT * E_DIM];    // fp16 inputs for GEMM
__device__ __half g_Wqh[(size_t)E_DIM * E_DIM];
__device__ __half g_Wkh[(size_t)E_DIM * E_DIM];
__device__ __half g_Wvh[(size_t)E_DIM * E_DIM];
__device__ __half g_Qh[(size_t)M_TOT * E_DIM];    // normalized fp16 Q (g folded)
__device__ __half g_Kh[(size_t)M_TOT * E_DIM];    // normalized fp16 K
__device__ __half g_Vt[(size_t)B_NUM * E_DIM * S_LEN]; // V^T: [(b*16+h)*64+d][s]

// ---------------- helpers ----------------
__device__ __forceinline__ void mma_f16(float c[4],
                                        unsigned a0, unsigned a1, unsigned a2, unsigned a3,
                                        unsigned b0, unsigned b1) {
    asm volatile(
        "mma.sync.aligned.m16n8k16.row.col.f32.f16.f16.f32 "
        "{%0,%1,%2,%3}, {%4,%5,%6,%7}, {%8,%9}, {%0,%1,%2,%3};"
        : "+f"(c[0]), "+f"(c[1]), "+f"(c[2]), "+f"(c[3])
        : "r"(a0), "r"(a1), "r"(a2), "r"(a3), "r"(b0), "r"(b1));
}

__device__ __forceinline__ void cp16(void* smem_dst, const void* gmem_src) {
    unsigned s = (unsigned)__cvta_generic_to_shared(smem_dst);
    asm volatile("cp.async.cg.shared.global [%0], [%1], 16;" :: "r"(s), "l"(gmem_src));
}
#define CP_COMMIT() asm volatile("cp.async.commit_group;")
#define CP_WAIT0()  asm volatile("cp.async.wait_group 0;")

// ---------------------------------------------------------------------------
// Kernel 0: fp32 -> fp16 conversion prepass.
// ---------------------------------------------------------------------------
__global__ void cvt_half(const float* __restrict__ src, __half* __restrict__ dst, int n4)
{
    int i = blockIdx.x * blockDim.x + threadIdx.x;
    if (i >= n4) return;
    float4 v = ((const float4*)src)[i];
    __half2* d = (__half2*)dst;
    d[2 * i]     = __floats2half2_rn(v.x, v.y);
    d[2 * i + 1] = __floats2half2_rn(v.z, v.w);
}

// ---------------------------------------------------------------------------
// Kernel 1: C = x @ W^T via m16n8k16 fp16 MMA (fp32 accum). Tile 128x128, BK=32.
// Smem stride 40 halfs (20 words, ==20 mod 32) => fragment LDS conflict-free.
// Epilogue trivial (writes fp32 Q/K/V).
// ---------------------------------------------------------------------------
#define ASH (128 * 40)   // halfs per tile buffer

__global__ __launch_bounds__(256, 2) void qkv_gemm()
{
    extern __shared__ __half smh[];
    __half* As[2] = { smh,           smh + ASH };
    __half* Bs[2] = { smh + 2*ASH,   smh + 3*ASH };

    const int z  = blockIdx.z;
    const __half* W = (z == 0) ? g_Wqh : (z == 1) ? g_Wkh : g_Wvh;
    float*        C = (z == 0) ? g_Q   : (z == 1) ? g_K   : g_V;

    const int m0   = blockIdx.y * 128;
    const int n0   = blockIdx.x * 128;
    const int t    = threadIdx.x;
    const int warp = t >> 5;
    const int lane = t & 31;
    const int wm   = warp >> 2;
    const int wn   = warp & 3;
    const int lr   = lane >> 2;
    const int lc   = lane & 3;

    float acc[4][4][4];
#pragma unroll
    for (int i = 0; i < 4; i++)
#pragma unroll
        for (int j = 0; j < 4; j++)
#pragma unroll
            for (int r = 0; r < 4; r++) acc[i][j][r] = 0.0f;

    auto prefetch = [&](int ks, int buf) {
        const int k0 = ks * 32;
#pragma unroll
        for (int i = 0; i < 2; i++) {
            int s   = t + i * 256;          // 0..511
            int row = s >> 2;               // 0..127
            int c4  = s & 3;                // 8-half chunk
            cp16(&As[buf][row * 40 + c4 * 8], &g_Xh[(size_t)(m0 + row) * E_DIM + k0 + c4 * 8]);
            cp16(&Bs[buf][row * 40 + c4 * 8], &W   [(size_t)(n0 + row) * E_DIM + k0 + c4 * 8]);
        }
    };

    prefetch(0, 0); CP_COMMIT();
    int buf = 0;

    for (int ks = 0; ks < 32; ks++) {
        CP_WAIT0();
        __syncthreads();
        if (ks + 1 < 32) { prefetch(ks + 1, buf ^ 1); CP_COMMIT(); }

#pragma unroll
        for (int kk = 0; kk < 2; kk++) {
            const int kb = kk * 16;
            unsigned af[4][4];
#pragma unroll
            for (int mi = 0; mi < 4; mi++) {
                int rb = wm * 64 + mi * 16 + lr;
                af[mi][0] = *(const unsigned*)&As[buf][rb       * 40 + kb + 2 * lc];
                af[mi][1] = *(const unsigned*)&As[buf][(rb + 8) * 40 + kb + 2 * lc];
                af[mi][2] = *(const unsigned*)&As[buf][rb       * 40 + kb + 2 * lc + 8];
                af[mi][3] = *(const unsigned*)&As[buf][(rb + 8) * 40 + kb + 2 * lc + 8];
            }
            unsigned bf[4][2];
#pragma unroll
            for (int ni = 0; ni < 4; ni++) {
                int nb = wn * 32 + ni * 8 + lr;
                bf[ni][0] = *(const unsigned*)&Bs[buf][nb * 40 + kb + 2 * lc];
                bf[ni][1] = *(const unsigned*)&Bs[buf][nb * 40 + kb + 2 * lc + 8];
            }
#pragma unroll
            for (int mi = 0; mi < 4; mi++)
#pragma unroll
                for (int ni = 0; ni < 4; ni++)
                    mma_f16(acc[mi][ni], af[mi][0], af[mi][1], af[mi][2], af[mi][3],
                            bf[ni][0], bf[ni][1]);
        }
        buf ^= 1;
    }

#pragma unroll
    for (int mi = 0; mi < 4; mi++) {
#pragma unroll
        for (int ni = 0; ni < 4; ni++) {
            int row = m0 + wm * 64 + mi * 16 + lr;
            int col = n0 + wn * 32 + ni * 8 + 2 * lc;
            *(float2*)&C[(size_t)row * E_DIM + col] =
                make_float2(acc[mi][ni][0], acc[mi][ni][1]);
            *(float2*)&C[(size_t)(row + 8) * E_DIM + col] =
                make_float2(acc[mi][ni][2], acc[mi][ni][3]);
        }
    }
}

// ---------------------------------------------------------------------------
// Kernel 2: per-head L2 norm (fp32 in), fold g into Q, write fp16.
// ---------------------------------------------------------------------------
__global__ __launch_bounds__(256) void norm_heads(const float* __restrict__ gptr)
{
    int warp = (blockIdx.x * blockDim.x + threadIdx.x) >> 5;
    int lane = threadIdx.x & 31;
    const int total = M_TOT * H_NUM;
    if (warp >= total) return;

    const float* src = (blockIdx.y == 0) ? g_Q  : g_K;
    __half*      dst = (blockIdx.y == 0) ? g_Qh : g_Kh;
    float        sc  = (blockIdx.y == 0) ? *gptr : 1.0f;

    const float* p = src + (size_t)warp * 64;
    float2 v = *(const float2*)&p[lane * 2];
    float ss = v.x * v.x + v.y * v.y;
#pragma unroll
    for (int m = 16; m > 0; m >>= 1) ss += __shfl_xor_sync(0xffffffffu, ss, m);
    float inv = sc / fmaxf(sqrtf(ss), 1e-12f);
    ((__half2*)(dst + (size_t)warp * 64))[lane] = __floats2half2_rn(v.x * inv, v.y * inv);
}

// ---------------------------------------------------------------------------
// Kernel 3: V transpose: g_V fp32 [b*2048+s][h*64+d] -> g_Vt fp16
// [(b*16+h)*64+d][s]. Tiled 32x32, conflict-free, coalesced both sides.
// ---------------------------------------------------------------------------
__global__ __launch_bounds__(256) void transpose_v()
{
    __shared__ float tile[32][33];
    const int s0 = blockIdx.x * 32;
    const int f0 = blockIdx.y * 32;
    const int b  = blockIdx.z;
    const int tx = threadIdx.x;      // 0..31
    const int ty = threadIdx.y;      // 0..7

#pragma unroll
    for (int j = 0; j < 32; j += 8)
        tile[ty + j][tx] = g_V[(size_t)(b * S_LEN + s0 + ty + j) * E_DIM + f0 + tx];
    __syncthreads();
#pragma unroll
    for (int j = 0; j < 32; j += 8)
        g_Vt[(size_t)(b * E_DIM + f0 + ty + j) * S_LEN + s0 + tx] =
            __float2half(tile[tx][ty + j]);
}

// ---------------------------------------------------------------------------
// Kernel 4: flash attention, fp16 MMA (m16n8k16), fp32 accum. Br=Bc=64.
// Warp-pair split: warp=(rpair,side), 16 rows x 32 cols each; pair covers 64.
// Q/P alias one smem tile. |score| <= |g| => fixed max M0, no rescaling.
// Strides 72 halfs (36 words == 4 mod 32) => all fragment LDS conflict-free.
// ---------------------------------------------------------------------------
#define TQ (64 * 72)                     // halfs per tile (Q/P, K, Vt)
#define LRED_BYTES 512
#define ATTN_SMEM (5 * TQ * 2 + LRED_BYTES)   // 46592 B

__global__ __launch_bounds__(256, 3) void attn_kernel(float* __restrict__ out,
                                                      const float* __restrict__ gptr)
{
    extern __shared__ __half smh[];
    __half* Qs     = smh;                 // aliased by Ps
    __half* Ps     = smh;
    __half* Ks[2]  = { smh + TQ,       smh + 2 * TQ };
    __half* Vts[2] = { smh + 3 * TQ,   smh + 4 * TQ };
    float*  lred   = (float*)(smh + 5 * TQ);   // 128 floats

    const int b     = blockIdx.z;
    const int h     = blockIdx.y;
    const int q0    = blockIdx.x * 64;
    const int t     = threadIdx.x;
    const int warp  = t >> 5;
    const int lane  = t & 31;
    const int lr    = lane >> 2;
    const int lc    = lane & 3;
    const int rpair = warp >> 1;
    const int side  = warp & 1;
    const int r0    = rpair * 16;
    const int c0    = side * 32;

    const float M0 = fabsf(gptr[0]);

    const __half* Qg  = g_Qh + ((size_t)(b * S_LEN) + q0) * E_DIM + h * D_HEAD;
    const __half* Kg  = g_Kh + (size_t)(b * S_LEN) * E_DIM + h * D_HEAD;
    const __half* Vtg = g_Vt + (size_t)(b * E_DIM + h * D_HEAD) * S_LEN;

    auto prefetch = [&](int kt, int bufi) {
#pragma unroll
        for (int i = 0; i < 2; i++) {
            int s  = t + i * 256;        // 0..511
            int r  = s >> 3;             // 0..63
            int c8 = s & 7;              // 8-half chunk
            cp16(&Ks[bufi][r * 72 + c8 * 8],
                 &Kg[(size_t)(kt * 64 + r) * E_DIM + c8 * 8]);
            cp16(&Vts[bufi][r * 72 + c8 * 8],
                 &Vtg[(size_t)r * S_LEN + kt * 64 + c8 * 8]);
        }
    };
    prefetch(0, 0); CP_COMMIT();

    // stage Q tile (64x64 halfs) once
#pragma unroll
    for (int i = 0; i < 2; i++) {
        int s  = t + i * 256;
        int r  = s >> 3;
        int c8 = s & 7;
        *(uint4*)&Qs[r * 72 + c8 * 8] = *(const uint4*)&Qg[(size_t)r * E_DIM + c8 * 8];
    }
    __syncthreads();

    unsigned qf[4][4];
#pragma unroll
    for (int kk = 0; kk < 4; kk++) {
        const int kb = kk * 16;
        int rb = r0 + lr;
        qf[kk][0] = *(const unsigned*)&Qs[rb       * 72 + kb + 2 * lc];
        qf[kk][1] = *(const unsigned*)&Qs[(rb + 8) * 72 + kb + 2 * lc];
        qf[kk][2] = *(const unsigned*)&Qs[rb       * 72 + kb + 2 * lc + 8];
        qf[kk][3] = *(const unsigned*)&Qs[(rb + 8) * 72 + kb + 2 * lc + 8];
    }
    // First Ps write is after the first in-loop __syncthreads => all warps
    // have extracted their Q fragments before Qs is overwritten.

    float oc[4][4];
#pragma unroll
    for (int ni = 0; ni < 4; ni++)
#pragma unroll
        for (int r = 0; r < 4; r++) oc[ni][r] = 0.0f;
    float l0 = 0.0f, l1 = 0.0f;

    int buf = 0;
    for (int kt = 0; kt < S_LEN / 64; kt++) {
        CP_WAIT0();
        __syncthreads();               // K/V ready; prev-iter Ps reads done
        if (kt + 1 < S_LEN / 64) { prefetch(kt + 1, buf ^ 1); CP_COMMIT(); }

        // ---- S = Q K^T  (rows r0..+15, cols c0..+31) ----
        float sv[4][4];
#pragma unroll
        for (int ni = 0; ni < 4; ni++)
#pragma unroll
            for (int r = 0; r < 4; r++) sv[ni][r] = 0.0f;

#pragma unroll
        for (int kk = 0; kk < 4; kk++) {
            const int kb = kk * 16;
#pragma unroll
            for (int ni = 0; ni < 4; ni++) {
                int nb = c0 + ni * 8 + lr;
                unsigned b0 = *(const unsigned*)&Ks[buf][nb * 72 + kb + 2 * lc];
                unsigned b1 = *(const unsigned*)&Ks[buf][nb * 72 + kb + 2 * lc + 8];
                mma_f16(sv[ni], qf[kk][0], qf[kk][1], qf[kk][2], qf[kk][3], b0, b1);
            }
        }

        // ---- P = exp(S - M0); stage own 32-col half as fp16 ----
#pragma unroll
        for (int ni = 0; ni < 4; ni++) {
            float p00 = __expf(sv[ni][0] - M0);
            float p01 = __expf(sv[ni][1] - M0);
            float p10 = __expf(sv[ni][2] - M0);
            float p11 = __expf(sv[ni][3] - M0);
            l0 += p00 + p01;
            l1 += p10 + p11;
            int col = c0 + ni * 8 + 2 * lc;
            *(__half2*)&Ps[(r0 + lr)     * 72 + col] = __floats2half2_rn(p00, p01);
            *(__half2*)&Ps[(r0 + lr + 8) * 72 + col] = __floats2half2_rn(p10, p11);
        }
        __syncthreads();               // both column-halves of P visible

        // ---- O += P @ V  (P rows over all 64 s; Vt rows = d cols c0..+31) ----
#pragma unroll
        for (int kk = 0; kk < 4; kk++) {
            const int kb = kk * 16;
            int rb = r0 + lr;
            unsigned a0 = *(const unsigned*)&Ps[rb       * 72 + kb + 2 * lc];
            unsigned a1 = *(const unsigned*)&Ps[(rb + 8) * 72 + kb + 2 * lc];
            unsigned a2 = *(const unsigned*)&Ps[rb       * 72 + kb + 2 * lc + 8];
            unsigned a3 = *(const unsigned*)&Ps[(rb + 8) * 72 + kb + 2 * lc + 8];
#pragma unroll
            for (int ni = 0; ni < 4; ni++) {
                int nb = c0 + ni * 8 + lr;
                unsigned b0 = *(const unsigned*)&Vts[buf][nb * 72 + kb + 2 * lc];
                unsigned b1 = *(const unsigned*)&Vts[buf][nb * 72 + kb + 2 * lc + 8];
                mma_f16(oc[ni], a0, a1, a2, a3, b0, b1);
            }
        }

        buf ^= 1;
    }

    // ---- epilogue: combine partner column-half row sums, normalize ----
    l0 += __shfl_xor_sync(0xffffffffu, l0, 1);
    l0 += __shfl_xor_sync(0xffffffffu, l0, 2);
    l1 += __shfl_xor_sync(0xffffffffu, l1, 1);
    l1 += __shfl_xor_sync(0xffffffffu, l1, 2);
    lred[warp * 16 + lr]     = l0;
    lred[warp * 16 + 8 + lr] = l1;
    __syncthreads();
    const int pw = warp ^ 1;
    float inv0 = 1.0f / (l0 + lred[pw * 16 + lr]);
    float inv1 = 1.0f / (l1 + lred[pw * 16 + 8 + lr]);

    int ra = q0 + r0 + lr;
#pragma unroll
    for (int ni = 0; ni < 4; ni++) {
        int col = h * D_HEAD + c0 + ni * 8 + 2 * lc;
        *(float2*)&out[((size_t)(b * S_LEN) + ra) * E_DIM + col] =
            make_float2(oc[ni][0] * inv0, oc[ni][1] * inv0);
        *(float2*)&out[((size_t)(b * S_LEN) + ra + 8) * E_DIM + col] =
            make_float2(oc[ni][2] * inv1, oc[ni][3] * inv1);
    }
}

// ---------------------------------------------------------------------------
extern "C" void kernel_launch(void* const* d_in, const int* in_sizes, int n_in,
                              void* d_out, int out_size)
{
    const float* x  = (const float*)d_in[0];
    const float* Wq = (const float*)d_in[1];
    const float* Wk = (const float*)d_in[2];
    const float* Wv = (const float*)d_in[3];
    const float* g  = (const float*)d_in[4];
    float* out = (float*)d_out;

    __half* hX;  cudaGetSymbolAddress((void**)&hX,  g_Xh);
    __half* hWq; cudaGetSymbolAddress((void**)&hWq, g_Wqh);
    __half* hWk; cudaGetSymbolAddress((void**)&hWk, g_Wkh);
    __half* hWv; cudaGetSymbolAddress((void**)&hWv, g_Wvh);

    // 0) fp32 -> fp16 conversion of GEMM inputs
    cvt_half<<<(M_TOT * E_DIM / 4 + 255) / 256, 256>>>(x,  hX,  M_TOT * E_DIM / 4);
    cvt_half<<<(E_DIM * E_DIM / 4 + 255) / 256, 256>>>(Wq, hWq, E_DIM * E_DIM / 4);
    cvt_half<<<(E_DIM * E_DIM / 4 + 255) / 256, 256>>>(Wk, hWk, E_DIM * E_DIM / 4);
    cvt_half<<<(E_DIM * E_DIM / 4 + 255) / 256, 256>>>(Wv, hWv, E_DIM * E_DIM / 4);

    // 1) QKV projections (fp16 MMA, fp32 accum/out)
    {
        size_t smem = (size_t)4 * ASH * sizeof(__half);    // 40960
        cudaFuncSetAttribute(qkv_gemm, cudaFuncAttributeMaxDynamicSharedMemorySize,
                             (int)smem);
        dim3 grid(E_DIM / 128, M_TOT / 128, 3);
        qkv_gemm<<<grid, 256, smem>>>();
    }

    // 2) per-head L2 norm -> fp16 Q/K (g folded into Q)
    {
        const int chunks = M_TOT * H_NUM;
        dim3 ngrid(chunks / 8, 2);
        norm_heads<<<ngrid, 256>>>(g);
    }

    // 3) V transpose -> fp16 [bh*64+d][s]
    {
        dim3 tgrid(S_LEN / 32, E_DIM / 32, B_NUM);
        dim3 tblk(32, 8);
        transpose_v<<<tgrid, tblk>>>();
    }

    // 4) Flash attention (fp16 MMA, 3 CTAs/SM)
    {
        cudaFuncSetAttribute(attn_kernel, cudaFuncAttributeMaxDynamicSharedMemorySize,
                             ATTN_SMEM);
        dim3 agrid(S_LEN / 64, H_NUM, B_NUM);
        attn_kernel<<<agrid, 256, ATTN_SMEM>>>(out, g);
    }
}

// round 10
// speedup vs baseline: 3.5567x; 1.3463x over previous
#include <cuda_runtime.h>
#include <cuda_fp16.h>
#include <math.h>

#define S_LEN  2048
#define E_DIM  1024
#define H_NUM  16
#define D_HEAD 64
#define B_NUM  2
#define M_TOT  (B_NUM * S_LEN)   // 4096

// ---------------- device scratch ----------------
__device__ float  g_Q[(size_t)M_TOT * E_DIM];     // fp32 projections
__device__ float  g_K[(size_t)M_TOT * E_DIM];
__device__ float  g_V[(size_t)M_TOT * E_DIM];
__device__ __half g_Xh[(size_t)M_TOT * E_DIM];    // fp16 inputs for GEMM
__device__ __half g_Wqh[(size_t)E_DIM * E_DIM];
__device__ __half g_Wkh[(size_t)E_DIM * E_DIM];
__device__ __half g_Wvh[(size_t)E_DIM * E_DIM];
__device__ __half g_Qh[(size_t)M_TOT * E_DIM];    // normalized fp16 Q (g folded)
__device__ __half g_Kh[(size_t)M_TOT * E_DIM];    // normalized fp16 K
__device__ __half g_Vt[(size_t)B_NUM * E_DIM * S_LEN]; // V^T: [(b*16+h)*64+d][s]

// ---------------- helpers ----------------
__device__ __forceinline__ void mma_f16(float c[4],
                                        unsigned a0, unsigned a1, unsigned a2, unsigned a3,
                                        unsigned b0, unsigned b1) {
    asm volatile(
        "mma.sync.aligned.m16n8k16.row.col.f32.f16.f16.f32 "
        "{%0,%1,%2,%3}, {%4,%5,%6,%7}, {%8,%9}, {%0,%1,%2,%3};"
        : "+f"(c[0]), "+f"(c[1]), "+f"(c[2]), "+f"(c[3])
        : "r"(a0), "r"(a1), "r"(a2), "r"(a3), "r"(b0), "r"(b1));
}

__device__ __forceinline__ void ldsm4(unsigned r[4], unsigned addr) {
    asm volatile("ldmatrix.sync.aligned.m8n8.x4.shared.b16 {%0,%1,%2,%3}, [%4];"
                 : "=r"(r[0]), "=r"(r[1]), "=r"(r[2]), "=r"(r[3]) : "r"(addr));
}

__device__ __forceinline__ void cp16(void* smem_dst, const void* gmem_src) {
    unsigned s = (unsigned)__cvta_generic_to_shared(smem_dst);
    asm volatile("cp.async.cg.shared.global [%0], [%1], 16;" :: "r"(s), "l"(gmem_src));
}
#define CP_COMMIT() asm volatile("cp.async.commit_group;")
#define CP_WAIT0()  asm volatile("cp.async.wait_group 0;")

// ---------------------------------------------------------------------------
// Kernel 0: fp32 -> fp16 conversion prepass.
// ---------------------------------------------------------------------------
__global__ void cvt_half(const float* __restrict__ src, __half* __restrict__ dst, int n4)
{
    int i = blockIdx.x * blockDim.x + threadIdx.x;
    if (i >= n4) return;
    float4 v = ((const float4*)src)[i];
    __half2* d = (__half2*)dst;
    d[2 * i]     = __floats2half2_rn(v.x, v.y);
    d[2 * i + 1] = __floats2half2_rn(v.z, v.w);
}

// ---------------------------------------------------------------------------
// Kernel 1: C = x @ W^T via m16n8k16 fp16 MMA (fp32 accum). Tile 128x128, BK=32.
// Fragments loaded with ldmatrix.x4 (12 LDSM/stage vs 48 LDS).
// Stride 40 halfs (20 words mod 32) => every LDSM phase hits all 32 banks once.
// ---------------------------------------------------------------------------
#define ASH (128 * 40)   // halfs per tile buffer

__global__ __launch_bounds__(256, 2) void qkv_gemm()
{
    extern __shared__ __half smh[];
    const unsigned smbase = (unsigned)__cvta_generic_to_shared(smh);
    const unsigned Abase[2] = { smbase,                smbase + ASH * 2 };
    const unsigned Bbase[2] = { smbase + 2 * ASH * 2,  smbase + 3 * ASH * 2 };
    __half* As[2] = { smh,           smh + ASH };
    __half* Bs[2] = { smh + 2*ASH,   smh + 3*ASH };

    const int z  = blockIdx.z;
    const __half* W = (z == 0) ? g_Wqh : (z == 1) ? g_Wkh : g_Wvh;
    float*        C = (z == 0) ? g_Q   : (z == 1) ? g_K   : g_V;

    const int m0   = blockIdx.y * 128;
    const int n0   = blockIdx.x * 128;
    const int t    = threadIdx.x;
    const int warp = t >> 5;
    const int lane = t & 31;
    const int wm   = warp >> 2;
    const int wn   = warp & 3;
    const int lr   = lane >> 2;
    const int lc   = lane & 3;

    // ldmatrix lane->row/col decomposition
    const int l7 = lane & 7;
    const int jA_row = (lane >> 3) & 1;    // +8 rows for tiles 1,3
    const int jA_col = (lane >> 4) & 1;    // +8 cols for tiles 2,3
    const int jB_row = (lane >> 4) & 1;    // +8 rows for tiles 2,3
    const int jB_col = (lane >> 3) & 1;    // +8 cols for tiles 1,3

    // per-lane byte offsets at kb=0
    unsigned aoff[4], boff[2];
#pragma unroll
    for (int mi = 0; mi < 4; mi++)
        aoff[mi] = ((wm * 64 + mi * 16 + jA_row * 8 + l7) * 40 + jA_col * 8) * 2;
#pragma unroll
    for (int nip = 0; nip < 2; nip++)
        boff[nip] = ((wn * 32 + nip * 16 + jB_row * 8 + l7) * 40 + jB_col * 8) * 2;

    float acc[4][4][4];
#pragma unroll
    for (int i = 0; i < 4; i++)
#pragma unroll
        for (int j = 0; j < 4; j++)
#pragma unroll
            for (int r = 0; r < 4; r++) acc[i][j][r] = 0.0f;

    auto prefetch = [&](int ks, int buf) {
        const int k0 = ks * 32;
#pragma unroll
        for (int i = 0; i < 2; i++) {
            int s   = t + i * 256;          // 0..511
            int row = s >> 2;               // 0..127
            int c4  = s & 3;                // 8-half chunk
            cp16(&As[buf][row * 40 + c4 * 8], &g_Xh[(size_t)(m0 + row) * E_DIM + k0 + c4 * 8]);
            cp16(&Bs[buf][row * 40 + c4 * 8], &W   [(size_t)(n0 + row) * E_DIM + k0 + c4 * 8]);
        }
    };

    prefetch(0, 0); CP_COMMIT();
    int buf = 0;

    for (int ks = 0; ks < 32; ks++) {
        CP_WAIT0();
        __syncthreads();
        if (ks + 1 < 32) { prefetch(ks + 1, buf ^ 1); CP_COMMIT(); }

#pragma unroll
        for (int kk = 0; kk < 2; kk++) {
            const unsigned kbb = kk * 32;   // 16 halfs = 32 bytes
            unsigned af[4][4];
#pragma unroll
            for (int mi = 0; mi < 4; mi++)
                ldsm4(af[mi], Abase[buf] + aoff[mi] + kbb);
            unsigned bfp[2][4];
#pragma unroll
            for (int nip = 0; nip < 2; nip++)
                ldsm4(bfp[nip], Bbase[buf] + boff[nip] + kbb);
#pragma unroll
            for (int mi = 0; mi < 4; mi++)
#pragma unroll
                for (int nip = 0; nip < 2; nip++) {
                    mma_f16(acc[mi][2 * nip],     af[mi][0], af[mi][1], af[mi][2], af[mi][3],
                            bfp[nip][0], bfp[nip][1]);
                    mma_f16(acc[mi][2 * nip + 1], af[mi][0], af[mi][1], af[mi][2], af[mi][3],
                            bfp[nip][2], bfp[nip][3]);
                }
        }
        buf ^= 1;
    }

#pragma unroll
    for (int mi = 0; mi < 4; mi++) {
#pragma unroll
        for (int ni = 0; ni < 4; ni++) {
            int row = m0 + wm * 64 + mi * 16 + lr;
            int col = n0 + wn * 32 + ni * 8 + 2 * lc;
            *(float2*)&C[(size_t)row * E_DIM + col] =
                make_float2(acc[mi][ni][0], acc[mi][ni][1]);
            *(float2*)&C[(size_t)(row + 8) * E_DIM + col] =
                make_float2(acc[mi][ni][2], acc[mi][ni][3]);
        }
    }
}

// ---------------------------------------------------------------------------
// Kernel 2: per-head L2 norm (fp32 in), fold g into Q, write fp16.
// ---------------------------------------------------------------------------
__global__ __launch_bounds__(256) void norm_heads(const float* __restrict__ gptr)
{
    int warp = (blockIdx.x * blockDim.x + threadIdx.x) >> 5;
    int lane = threadIdx.x & 31;
    const int total = M_TOT * H_NUM;
    if (warp >= total) return;

    const float* src = (blockIdx.y == 0) ? g_Q  : g_K;
    __half*      dst = (blockIdx.y == 0) ? g_Qh : g_Kh;
    float        sc  = (blockIdx.y == 0) ? *gptr : 1.0f;

    const float* p = src + (size_t)warp * 64;
    float2 v = *(const float2*)&p[lane * 2];
    float ss = v.x * v.x + v.y * v.y;
#pragma unroll
    for (int m = 16; m > 0; m >>= 1) ss += __shfl_xor_sync(0xffffffffu, ss, m);
    float inv = sc / fmaxf(sqrtf(ss), 1e-12f);
    ((__half2*)(dst + (size_t)warp * 64))[lane] = __floats2half2_rn(v.x * inv, v.y * inv);
}

// ---------------------------------------------------------------------------
// Kernel 3: V transpose: g_V fp32 [b*2048+s][h*64+d] -> g_Vt fp16
// [(b*16+h)*64+d][s]. Tiled 32x32, conflict-free, coalesced both sides.
// ---------------------------------------------------------------------------
__global__ __launch_bounds__(256) void transpose_v()
{
    __shared__ float tile[32][33];
    const int s0 = blockIdx.x * 32;
    const int f0 = blockIdx.y * 32;
    const int b  = blockIdx.z;
    const int tx = threadIdx.x;      // 0..31
    const int ty = threadIdx.y;      // 0..7

#pragma unroll
    for (int j = 0; j < 32; j += 8)
        tile[ty + j][tx] = g_V[(size_t)(b * S_LEN + s0 + ty + j) * E_DIM + f0 + tx];
    __syncthreads();
#pragma unroll
    for (int j = 0; j < 32; j += 8)
        g_Vt[(size_t)(b * E_DIM + f0 + ty + j) * S_LEN + s0 + tx] =
            __float2half(tile[tx][ty + j]);
}

// ---------------------------------------------------------------------------
// Kernel 4: flash attention, fp16 MMA + ldmatrix. Br=Bc=64, warp-pair split.
// Q/P alias one smem tile. Fixed max M0 (|score| <= |g|), no rescaling.
// Stride 72 halfs (36 words == 4 mod 32) => LDSM/LDS conflict-free.
// ---------------------------------------------------------------------------
#define TQ (64 * 72)                     // halfs per tile (Q/P, K, Vt)
#define LRED_BYTES 512
#define ATTN_SMEM (5 * TQ * 2 + LRED_BYTES)   // 46592 B

__global__ __launch_bounds__(256, 3) void attn_kernel(float* __restrict__ out,
                                                      const float* __restrict__ gptr)
{
    extern __shared__ __half smh[];
    const unsigned smbase = (unsigned)__cvta_generic_to_shared(smh);
    __half* Qs     = smh;                 // aliased by Ps
    __half* Ps     = smh;
    const unsigned PsB    = smbase;
    __half* Ks[2]  = { smh + TQ,       smh + 2 * TQ };
    const unsigned KsB[2] = { smbase + TQ * 2,     smbase + 2 * TQ * 2 };
    __half* Vts[2] = { smh + 3 * TQ,   smh + 4 * TQ };
    const unsigned VtB[2] = { smbase + 3 * TQ * 2, smbase + 4 * TQ * 2 };
    float*  lred   = (float*)(smh + 5 * TQ);   // 128 floats

    const int b     = blockIdx.z;
    const int h     = blockIdx.y;
    const int q0    = blockIdx.x * 64;
    const int t     = threadIdx.x;
    const int warp  = t >> 5;
    const int lane  = t & 31;
    const int lr    = lane >> 2;
    const int lc    = lane & 3;
    const int rpair = warp >> 1;
    const int side  = warp & 1;
    const int r0    = rpair * 16;
    const int c0    = side * 32;

    const int l7 = lane & 7;
    const int jA_row = (lane >> 3) & 1;
    const int jA_col = (lane >> 4) & 1;
    const int jB_row = (lane >> 4) & 1;
    const int jB_col = (lane >> 3) & 1;

    // per-lane LDSM byte offsets at kb=0
    const unsigned aoff = ((r0 + jA_row * 8 + l7) * 72 + jA_col * 8) * 2;    // A (Q/P rows)
    unsigned noff[2];
#pragma unroll
    for (int nip = 0; nip < 2; nip++)
        noff[nip] = ((c0 + nip * 16 + jB_row * 8 + l7) * 72 + jB_col * 8) * 2; // B (K/Vt rows)

    const float M0 = fabsf(gptr[0]);

    const __half* Qg  = g_Qh + ((size_t)(b * S_LEN) + q0) * E_DIM + h * D_HEAD;
    const __half* Kg  = g_Kh + (size_t)(b * S_LEN) * E_DIM + h * D_HEAD;
    const __half* Vtg = g_Vt + (size_t)(b * E_DIM + h * D_HEAD) * S_LEN;

    auto prefetch = [&](int kt, int bufi) {
#pragma unroll
        for (int i = 0; i < 2; i++) {
            int s  = t + i * 256;        // 0..511
            int r  = s >> 3;             // 0..63
            int c8 = s & 7;              // 8-half chunk
            cp16(&Ks[bufi][r * 72 + c8 * 8],
                 &Kg[(size_t)(kt * 64 + r) * E_DIM + c8 * 8]);
            cp16(&Vts[bufi][r * 72 + c8 * 8],
                 &Vtg[(size_t)r * S_LEN + kt * 64 + c8 * 8]);
        }
    };
    prefetch(0, 0); CP_COMMIT();

    // stage Q tile (64x64 halfs) once
#pragma unroll
    for (int i = 0; i < 2; i++) {
        int s  = t + i * 256;
        int r  = s >> 3;
        int c8 = s & 7;
        *(uint4*)&Qs[r * 72 + c8 * 8] = *(const uint4*)&Qg[(size_t)r * E_DIM + c8 * 8];
    }
    __syncthreads();

    unsigned qf[4][4];
#pragma unroll
    for (int kk = 0; kk < 4; kk++)
        ldsm4(qf[kk], PsB + aoff + kk * 32);
    // First Ps write is after the first in-loop __syncthreads => all warps
    // have extracted their Q fragments before Qs is overwritten.

    float oc[4][4];
#pragma unroll
    for (int ni = 0; ni < 4; ni++)
#pragma unroll
        for (int r = 0; r < 4; r++) oc[ni][r] = 0.0f;
    float l0 = 0.0f, l1 = 0.0f;

    int buf = 0;
    for (int kt = 0; kt < S_LEN / 64; kt++) {
        CP_WAIT0();
        __syncthreads();               // K/V ready; prev-iter Ps reads done
        if (kt + 1 < S_LEN / 64) { prefetch(kt + 1, buf ^ 1); CP_COMMIT(); }

        // ---- S = Q K^T  (rows r0..+15, cols c0..+31) ----
        float sv[4][4];
#pragma unroll
        for (int ni = 0; ni < 4; ni++)
#pragma unroll
            for (int r = 0; r < 4; r++) sv[ni][r] = 0.0f;

#pragma unroll
        for (int kk = 0; kk < 4; kk++) {
            const unsigned kbb = kk * 32;
#pragma unroll
            for (int nip = 0; nip < 2; nip++) {
                unsigned bfp[4];
                ldsm4(bfp, KsB[buf] + noff[nip] + kbb);
                mma_f16(sv[2 * nip],     qf[kk][0], qf[kk][1], qf[kk][2], qf[kk][3],
                        bfp[0], bfp[1]);
                mma_f16(sv[2 * nip + 1], qf[kk][0], qf[kk][1], qf[kk][2], qf[kk][3],
                        bfp[2], bfp[3]);
            }
        }

        // ---- P = exp(S - M0); stage own 32-col half as fp16 ----
#pragma unroll
        for (int ni = 0; ni < 4; ni++) {
            float p00 = __expf(sv[ni][0] - M0);
            float p01 = __expf(sv[ni][1] - M0);
            float p10 = __expf(sv[ni][2] - M0);
            float p11 = __expf(sv[ni][3] - M0);
            l0 += p00 + p01;
            l1 += p10 + p11;
            int col = c0 + ni * 8 + 2 * lc;
            *(__half2*)&Ps[(r0 + lr)     * 72 + col] = __floats2half2_rn(p00, p01);
            *(__half2*)&Ps[(r0 + lr + 8) * 72 + col] = __floats2half2_rn(p10, p11);
        }
        __syncthreads();               // both column-halves of P visible

        // ---- O += P @ V  (P rows over all 64 s; Vt rows = d cols c0..+31) ----
#pragma unroll
        for (int kk = 0; kk < 4; kk++) {
            const unsigned kbb = kk * 32;
            unsigned af[4];
            ldsm4(af, PsB + aoff + kbb);
#pragma unroll
            for (int nip = 0; nip < 2; nip++) {
                unsigned bfp[4];
                ldsm4(bfp, VtB[buf] + noff[nip] + kbb);
                mma_f16(oc[2 * nip],     af[0], af[1], af[2], af[3], bfp[0], bfp[1]);
                mma_f16(oc[2 * nip + 1], af[0], af[1], af[2], af[3], bfp[2], bfp[3]);
            }
        }

        buf ^= 1;
    }

    // ---- epilogue: combine partner column-half row sums, normalize ----
    l0 += __shfl_xor_sync(0xffffffffu, l0, 1);
    l0 += __shfl_xor_sync(0xffffffffu, l0, 2);
    l1 += __shfl_xor_sync(0xffffffffu, l1, 1);
    l1 += __shfl_xor_sync(0xffffffffu, l1, 2);
    lred[warp * 16 + lr]     = l0;
    lred[warp * 16 + 8 + lr] = l1;
    __syncthreads();
    const int pw = warp ^ 1;
    float inv0 = 1.0f / (l0 + lred[pw * 16 + lr]);
    float inv1 = 1.0f / (l1 + lred[pw * 16 + 8 + lr]);

    int ra = q0 + r0 + lr;
#pragma unroll
    for (int ni = 0; ni < 4; ni++) {
        int col = h * D_HEAD + c0 + ni * 8 + 2 * lc;
        *(float2*)&out[((size_t)(b * S_LEN) + ra) * E_DIM + col] =
            make_float2(oc[ni][0] * inv0, oc[ni][1] * inv0);
        *(float2*)&out[((size_t)(b * S_LEN) + ra + 8) * E_DIM + col] =
            make_float2(oc[ni][2] * inv1, oc[ni][3] * inv1);
    }
}

// ---------------------------------------------------------------------------
extern "C" void kernel_launch(void* const* d_in, const int* in_sizes, int n_in,
                              void* d_out, int out_size)
{
    const float* x  = (const float*)d_in[0];
    const float* Wq = (const float*)d_in[1];
    const float* Wk = (const float*)d_in[2];
    const float* Wv = (const float*)d_in[3];
    const float* g  = (const float*)d_in[4];
    float* out = (float*)d_out;

    __half* hX;  cudaGetSymbolAddress((void**)&hX,  g_Xh);
    __half* hWq; cudaGetSymbolAddress((void**)&hWq, g_Wqh);
    __half* hWk; cudaGetSymbolAddress((void**)&hWk, g_Wkh);
    __half* hWv; cudaGetSymbolAddress((void**)&hWv, g_Wvh);

    // 0) fp32 -> fp16 conversion of GEMM inputs
    cvt_half<<<(M_TOT * E_DIM / 4 + 255) / 256, 256>>>(x,  hX,  M_TOT * E_DIM / 4);
    cvt_half<<<(E_DIM * E_DIM / 4 + 255) / 256, 256>>>(Wq, hWq, E_DIM * E_DIM / 4);
    cvt_half<<<(E_DIM * E_DIM / 4 + 255) / 256, 256>>>(Wk, hWk, E_DIM * E_DIM / 4);
    cvt_half<<<(E_DIM * E_DIM / 4 + 255) / 256, 256>>>(Wv, hWv, E_DIM * E_DIM / 4);

    // 1) QKV projections (fp16 MMA + ldmatrix)
    {
        size_t smem = (size_t)4 * ASH * sizeof(__half);    // 40960
        cudaFuncSetAttribute(qkv_gemm, cudaFuncAttributeMaxDynamicSharedMemorySize,
                             (int)smem);
        dim3 grid(E_DIM / 128, M_TOT / 128, 3);
        qkv_gemm<<<grid, 256, smem>>>();
    }

    // 2) per-head L2 norm -> fp16 Q/K (g folded into Q)
    {
        const int chunks = M_TOT * H_NUM;
        dim3 ngrid(chunks / 8, 2);
        norm_heads<<<ngrid, 256>>>(g);
    }

    // 3) V transpose -> fp16 [bh*64+d][s]
    {
        dim3 tgrid(S_LEN / 32, E_DIM / 32, B_NUM);
        dim3 tblk(32, 8);
        transpose_v<<<tgrid, tblk>>>();
    }

    // 4) Flash attention (fp16 MMA + ldmatrix, 3 CTAs/SM)
    {
        cudaFuncSetAttribute(attn_kernel, cudaFuncAttributeMaxDynamicSharedMemorySize,
                             ATTN_SMEM);
        dim3 agrid(S_LEN / 64, H_NUM, B_NUM);
        attn_kernel<<<agrid, 256, ATTN_SMEM>>>(out, g);
    }
}

// round 13
// speedup vs baseline: 3.6187x; 1.0174x over previous
#include <cuda_runtime.h>
#include <cuda_fp16.h>
#include <math.h>

#define S_LEN  2048
#define E_DIM  1024
#define H_NUM  16
#define D_HEAD 64
#define B_NUM  2
#define M_TOT  (B_NUM * S_LEN)   // 4096

// ---------------- device scratch (all fp16 intermediates) ----------------
__device__ __half g_Xh[(size_t)M_TOT * E_DIM];    // fp16 x
__device__ __half g_Wqh[(size_t)E_DIM * E_DIM];
__device__ __half g_Wkh[(size_t)E_DIM * E_DIM];
__device__ __half g_Wvh[(size_t)E_DIM * E_DIM];
__device__ __half g_Qr[(size_t)M_TOT * E_DIM];    // raw fp16 projections
__device__ __half g_Kr[(size_t)M_TOT * E_DIM];
__device__ __half g_Vh[(size_t)M_TOT * E_DIM];
__device__ __half g_Qh[(size_t)M_TOT * E_DIM];    // normalized fp16 Q (g folded)
__device__ __half g_Kh[(size_t)M_TOT * E_DIM];    // normalized fp16 K
__device__ __half g_Vt[(size_t)B_NUM * E_DIM * S_LEN]; // V^T: [(b*16+h)*64+d][s]

// ---------------- helpers ----------------
__device__ __forceinline__ void mma_f16(float c[4],
                                        unsigned a0, unsigned a1, unsigned a2, unsigned a3,
                                        unsigned b0, unsigned b1) {
    asm volatile(
        "mma.sync.aligned.m16n8k16.row.col.f32.f16.f16.f32 "
        "{%0,%1,%2,%3}, {%4,%5,%6,%7}, {%8,%9}, {%0,%1,%2,%3};"
        : "+f"(c[0]), "+f"(c[1]), "+f"(c[2]), "+f"(c[3])
        : "r"(a0), "r"(a1), "r"(a2), "r"(a3), "r"(b0), "r"(b1));
}

__device__ __forceinline__ void ldsm4(unsigned r[4], unsigned addr) {
    asm volatile("ldmatrix.sync.aligned.m8n8.x4.shared.b16 {%0,%1,%2,%3}, [%4];"
                 : "=r"(r[0]), "=r"(r[1]), "=r"(r[2]), "=r"(r[3]) : "r"(addr));
}

__device__ __forceinline__ void cp16(void* smem_dst, const void* gmem_src) {
    unsigned s = (unsigned)__cvta_generic_to_shared(smem_dst);
    asm volatile("cp.async.cg.shared.global [%0], [%1], 16;" :: "r"(s), "l"(gmem_src));
}
#define CP_COMMIT() asm volatile("cp.async.commit_group;")
#define CP_WAIT0()  asm volatile("cp.async.wait_group 0;")

__device__ __forceinline__ unsigned pack_h2(float a, float b) {
    __half2 h = __floats2half2_rn(a, b);
    return *(unsigned*)&h;
}

// ---------------------------------------------------------------------------
// Kernel 0: one-shot fp32 -> fp16 conversion for x, Wq, Wk, Wv.
// ---------------------------------------------------------------------------
#define NX4 (M_TOT * E_DIM / 4)     // 1048576
#define NW4 (E_DIM * E_DIM / 4)     // 262144
#define NCVT (NX4 + 3 * NW4)        // 1835008

__global__ void cvt_all(const float* __restrict__ x,  const float* __restrict__ wq,
                        const float* __restrict__ wk, const float* __restrict__ wv)
{
    int i = blockIdx.x * blockDim.x + threadIdx.x;
    if (i >= NCVT) return;
    const float* src;
    __half* dst;
    int j;
    if (i < NX4)                  { src = x;  dst = g_Xh;  j = i; }
    else if (i < NX4 + NW4)       { src = wq; dst = g_Wqh; j = i - NX4; }
    else if (i < NX4 + 2 * NW4)   { src = wk; dst = g_Wkh; j = i - NX4 - NW4; }
    else                          { src = wv; dst = g_Wvh; j = i - NX4 - 2 * NW4; }
    float4 v = ((const float4*)src)[j];
    __half2* d = (__half2*)dst;
    d[2 * j]     = __floats2half2_rn(v.x, v.y);
    d[2 * j + 1] = __floats2half2_rn(v.z, v.w);
}

// ---------------------------------------------------------------------------
// Kernel 1: C = x @ W^T via m16n8k16 fp16 MMA + ldmatrix. Tile 128x128, BK=32.
// Epilogue writes fp16 (raw, pre-norm). Stride 40 halfs => conflict-free.
// ---------------------------------------------------------------------------
#define ASH (128 * 40)   // halfs per tile buffer

__global__ __launch_bounds__(256, 2) void qkv_gemm()
{
    extern __shared__ __half smh[];
    const unsigned smbase = (unsigned)__cvta_generic_to_shared(smh);
    const unsigned Abase[2] = { smbase,                smbase + ASH * 2 };
    const unsigned Bbase[2] = { smbase + 2 * ASH * 2,  smbase + 3 * ASH * 2 };
    __half* As[2] = { smh,           smh + ASH };
    __half* Bs[2] = { smh + 2*ASH,   smh + 3*ASH };

    const int z  = blockIdx.z;
    const __half* W = (z == 0) ? g_Wqh : (z == 1) ? g_Wkh : g_Wvh;
    __half*       C = (z == 0) ? g_Qr  : (z == 1) ? g_Kr  : g_Vh;

    const int m0   = blockIdx.y * 128;
    const int n0   = blockIdx.x * 128;
    const int t    = threadIdx.x;
    const int warp = t >> 5;
    const int lane = t & 31;
    const int wm   = warp >> 2;
    const int wn   = warp & 3;
    const int lr   = lane >> 2;
    const int lc   = lane & 3;

    const int l7 = lane & 7;
    const int jA_row = (lane >> 3) & 1;
    const int jA_col = (lane >> 4) & 1;
    const int jB_row = (lane >> 4) & 1;
    const int jB_col = (lane >> 3) & 1;

    unsigned aoff[4], boff[2];
#pragma unroll
    for (int mi = 0; mi < 4; mi++)
        aoff[mi] = ((wm * 64 + mi * 16 + jA_row * 8 + l7) * 40 + jA_col * 8) * 2;
#pragma unroll
    for (int nip = 0; nip < 2; nip++)
        boff[nip] = ((wn * 32 + nip * 16 + jB_row * 8 + l7) * 40 + jB_col * 8) * 2;

    float acc[4][4][4];
#pragma unroll
    for (int i = 0; i < 4; i++)
#pragma unroll
        for (int j = 0; j < 4; j++)
#pragma unroll
            for (int r = 0; r < 4; r++) acc[i][j][r] = 0.0f;

    auto prefetch = [&](int ks, int buf) {
        const int k0 = ks * 32;
#pragma unroll
        for (int i = 0; i < 2; i++) {
            int s   = t + i * 256;
            int row = s >> 2;
            int c4  = s & 3;
            cp16(&As[buf][row * 40 + c4 * 8], &g_Xh[(size_t)(m0 + row) * E_DIM + k0 + c4 * 8]);
            cp16(&Bs[buf][row * 40 + c4 * 8], &W   [(size_t)(n0 + row) * E_DIM + k0 + c4 * 8]);
        }
    };

    prefetch(0, 0); CP_COMMIT();
    int buf = 0;

    for (int ks = 0; ks < 32; ks++) {
        CP_WAIT0();
        __syncthreads();
        if (ks + 1 < 32) { prefetch(ks + 1, buf ^ 1); CP_COMMIT(); }

#pragma unroll
        for (int kk = 0; kk < 2; kk++) {
            const unsigned kbb = kk * 32;
            unsigned af[4][4];
#pragma unroll
            for (int mi = 0; mi < 4; mi++)
                ldsm4(af[mi], Abase[buf] + aoff[mi] + kbb);
            unsigned bfp[2][4];
#pragma unroll
            for (int nip = 0; nip < 2; nip++)
                ldsm4(bfp[nip], Bbase[buf] + boff[nip] + kbb);
#pragma unroll
            for (int mi = 0; mi < 4; mi++)
#pragma unroll
                for (int nip = 0; nip < 2; nip++) {
                    mma_f16(acc[mi][2 * nip],     af[mi][0], af[mi][1], af[mi][2], af[mi][3],
                            bfp[nip][0], bfp[nip][1]);
                    mma_f16(acc[mi][2 * nip + 1], af[mi][0], af[mi][1], af[mi][2], af[mi][3],
                            bfp[nip][2], bfp[nip][3]);
                }
        }
        buf ^= 1;
    }

#pragma unroll
    for (int mi = 0; mi < 4; mi++) {
#pragma unroll
        for (int ni = 0; ni < 4; ni++) {
            int row = m0 + wm * 64 + mi * 16 + lr;
            int col = n0 + wn * 32 + ni * 8 + 2 * lc;
            *(__half2*)&C[(size_t)row * E_DIM + col] =
                __floats2half2_rn(acc[mi][ni][0], acc[mi][ni][1]);
            *(__half2*)&C[(size_t)(row + 8) * E_DIM + col] =
                __floats2half2_rn(acc[mi][ni][2], acc[mi][ni][3]);
        }
    }
}

// ---------------------------------------------------------------------------
// Kernel 2: per-head L2 norm (fp16 in, fp32 math), fold g into Q, fp16 out.
// ---------------------------------------------------------------------------
__global__ __launch_bounds__(256) void norm_heads(const float* __restrict__ gptr)
{
    int warp = (blockIdx.x * blockDim.x + threadIdx.x) >> 5;
    int lane = threadIdx.x & 31;
    const int total = M_TOT * H_NUM;
    if (warp >= total) return;

    const __half* src = (blockIdx.y == 0) ? g_Qr : g_Kr;
    __half*       dst = (blockIdx.y == 0) ? g_Qh : g_Kh;
    float         sc  = (blockIdx.y == 0) ? *gptr : 1.0f;

    __half2 v = ((const __half2*)(src + (size_t)warp * 64))[lane];
    float2 vf = __half22float2(v);
    float ss = vf.x * vf.x + vf.y * vf.y;
#pragma unroll
    for (int m = 16; m > 0; m >>= 1) ss += __shfl_xor_sync(0xffffffffu, ss, m);
    float inv = sc / fmaxf(sqrtf(ss), 1e-12f);
    ((__half2*)(dst + (size_t)warp * 64))[lane] = __floats2half2_rn(vf.x * inv, vf.y * inv);
}

// ---------------------------------------------------------------------------
// Kernel 3: V transpose fp16->fp16: g_Vh [b*2048+s][f] -> g_Vt [(b*E+f)][s].
// Block: 32 s x 64 f. half2 loads; smem tile half[32][66] (odd word stride).
// ---------------------------------------------------------------------------
__global__ __launch_bounds__(256) void transpose_v()
{
    __shared__ __half tile[32][66];
    const int s0 = blockIdx.x * 32;
    const int f0 = blockIdx.y * 64;
    const int b  = blockIdx.z;
    const int tx = threadIdx.x;      // 0..31
    const int ty = threadIdx.y;      // 0..7
    const int tid = ty * 32 + tx;

#pragma unroll
    for (int j = 0; j < 4; j++) {
        int r = ty + 8 * j;
        *(__half2*)&tile[r][2 * tx] =
            *(const __half2*)&g_Vh[(size_t)(b * S_LEN + s0 + r) * E_DIM + f0 + 2 * tx];
    }
    __syncthreads();

    const int f  = tid >> 2;         // 0..63
    const int sp0 = (tid & 3) * 4;   // 4 s-pairs per thread
#pragma unroll
    for (int k = 0; k < 4; k++) {
        int sp = sp0 + k;
        __half2 v = __halves2half2(tile[2 * sp][f], tile[2 * sp + 1][f]);
        *(__half2*)&g_Vt[(size_t)(b * E_DIM + f0 + f) * S_LEN + s0 + 2 * sp] = v;
    }
}

// ---------------------------------------------------------------------------
// Kernel 4: flash attention, fp16 MMA + ldmatrix. Br=Bc=64, warp-pair split.
// PV reuses own P half from registers (FA2 C->A fragment identity); only the
// partner half is re-loaded via ldmatrix. Fixed max M0, no rescaling.
// ---------------------------------------------------------------------------
#define TQ (64 * 72)                     // halfs per tile (Q/P, K, Vt)
#define LRED_BYTES 512
#define ATTN_SMEM (5 * TQ * 2 + LRED_BYTES)   // 46592 B

__global__ __launch_bounds__(256, 3) void attn_kernel(float* __restrict__ out,
                                                      const float* __restrict__ gptr)
{
    extern __shared__ __half smh[];
    const unsigned smbase = (unsigned)__cvta_generic_to_shared(smh);
    __half* Qs     = smh;                 // aliased by Ps
    __half* Ps     = smh;
    const unsigned PsB    = smbase;
    __half* Ks[2]  = { smh + TQ,       smh + 2 * TQ };
    const unsigned KsB[2] = { smbase + TQ * 2,     smbase + 2 * TQ * 2 };
    __half* Vts[2] = { smh + 3 * TQ,   smh + 4 * TQ };
    const unsigned VtB[2] = { smbase + 3 * TQ * 2, smbase + 4 * TQ * 2 };
    float*  lred   = (float*)(smh + 5 * TQ);   // 128 floats

    const int b     = blockIdx.z;
    const int h     = blockIdx.y;
    const int q0    = blockIdx.x * 64;
    const int t     = threadIdx.x;
    const int warp  = t >> 5;
    const int lane  = t & 31;
    const int lr    = lane >> 2;
    const int lc    = lane & 3;
    const int rpair = warp >> 1;
    const int side  = warp & 1;
    const int r0    = rpair * 16;
    const int c0    = side * 32;

    const int l7 = lane & 7;
    const int jA_row = (lane >> 3) & 1;
    const int jA_col = (lane >> 4) & 1;
    const int jB_row = (lane >> 4) & 1;
    const int jB_col = (lane >> 3) & 1;

    const unsigned aoff = ((r0 + jA_row * 8 + l7) * 72 + jA_col * 8) * 2;
    unsigned noff[2];
#pragma unroll
    for (int nip = 0; nip < 2; nip++)
        noff[nip] = ((c0 + nip * 16 + jB_row * 8 + l7) * 72 + jB_col * 8) * 2;

    const float M0 = fabsf(gptr[0]);

    const __half* Qg  = g_Qh + ((size_t)(b * S_LEN) + q0) * E_DIM + h * D_HEAD;
    const __half* Kg  = g_Kh + (size_t)(b * S_LEN) * E_DIM + h * D_HEAD;
    const __half* Vtg = g_Vt + (size_t)(b * E_DIM + h * D_HEAD) * S_LEN;

    auto prefetch = [&](int kt, int bufi) {
#pragma unroll
        for (int i = 0; i < 2; i++) {
            int s  = t + i * 256;
            int r  = s >> 3;
            int c8 = s & 7;
            cp16(&Ks[bufi][r * 72 + c8 * 8],
                 &Kg[(size_t)(kt * 64 + r) * E_DIM + c8 * 8]);
            cp16(&Vts[bufi][r * 72 + c8 * 8],
                 &Vtg[(size_t)r * S_LEN + kt * 64 + c8 * 8]);
        }
    };
    prefetch(0, 0); CP_COMMIT();

#pragma unroll
    for (int i = 0; i < 2; i++) {
        int s  = t + i * 256;
        int r  = s >> 3;
        int c8 = s & 7;
        *(uint4*)&Qs[r * 72 + c8 * 8] = *(const uint4*)&Qg[(size_t)r * E_DIM + c8 * 8];
    }
    __syncthreads();

    unsigned qf[4][4];
#pragma unroll
    for (int kk = 0; kk < 4; kk++)
        ldsm4(qf[kk], PsB + aoff + kk * 32);
    // First Ps write happens after the first in-loop __syncthreads.

    float oc[4][4];
#pragma unroll
    for (int ni = 0; ni < 4; ni++)
#pragma unroll
        for (int r = 0; r < 4; r++) oc[ni][r] = 0.0f;
    float l0 = 0.0f, l1 = 0.0f;

    const int okk = c0 >> 4;            // own first kk block in PV (0 or 2)
    const int pkk = (c0 ^ 32) >> 4;     // partner's first kk block

    int buf = 0;
    for (int kt = 0; kt < S_LEN / 64; kt++) {
        CP_WAIT0();
        __syncthreads();
        if (kt + 1 < S_LEN / 64) { prefetch(kt + 1, buf ^ 1); CP_COMMIT(); }

        // ---- S = Q K^T ----
        float sv[4][4];
#pragma unroll
        for (int ni = 0; ni < 4; ni++)
#pragma unroll
            for (int r = 0; r < 4; r++) sv[ni][r] = 0.0f;

#pragma unroll
        for (int kk = 0; kk < 4; kk++) {
            const unsigned kbb = kk * 32;
#pragma unroll
            for (int nip = 0; nip < 2; nip++) {
                unsigned bfp[4];
                ldsm4(bfp, KsB[buf] + noff[nip] + kbb);
                mma_f16(sv[2 * nip],     qf[kk][0], qf[kk][1], qf[kk][2], qf[kk][3],
                        bfp[0], bfp[1]);
                mma_f16(sv[2 * nip + 1], qf[kk][0], qf[kk][1], qf[kk][2], qf[kk][3],
                        bfp[2], bfp[3]);
            }
        }

        // ---- P = exp(S - M0): keep own half packed in regs AND stage it ----
        unsigned pk0[4], pk1[4];
#pragma unroll
        for (int ni = 0; ni < 4; ni++) {
            float p00 = __expf(sv[ni][0] - M0);
            float p01 = __expf(sv[ni][1] - M0);
            float p10 = __expf(sv[ni][2] - M0);
            float p11 = __expf(sv[ni][3] - M0);
            l0 += p00 + p01;
            l1 += p10 + p11;
            pk0[ni] = pack_h2(p00, p01);
            pk1[ni] = pack_h2(p10, p11);
            int col = c0 + ni * 8 + 2 * lc;
            *(unsigned*)&Ps[(r0 + lr)     * 72 + col] = pk0[ni];
            *(unsigned*)&Ps[(r0 + lr + 8) * 72 + col] = pk1[ni];
        }
        __syncthreads();               // partner half of P visible

        // ---- O += P @ V ----
#pragma unroll
        for (int j = 0; j < 2; j++) {
            // own kk block: A-frag directly from registers (C->A identity)
            {
                const unsigned kbb = (okk + j) * 32;
#pragma unroll
                for (int nip = 0; nip < 2; nip++) {
                    unsigned bfp[4];
                    ldsm4(bfp, VtB[buf] + noff[nip] + kbb);
                    mma_f16(oc[2 * nip],     pk0[2*j], pk1[2*j], pk0[2*j+1], pk1[2*j+1],
                            bfp[0], bfp[1]);
                    mma_f16(oc[2 * nip + 1], pk0[2*j], pk1[2*j], pk0[2*j+1], pk1[2*j+1],
                            bfp[2], bfp[3]);
                }
            }
            // partner kk block: A-frag via ldmatrix from Ps
            {
                const unsigned kbb = (pkk + j) * 32;
                unsigned af[4];
                ldsm4(af, PsB + aoff + kbb);
#pragma unroll
                for (int nip = 0; nip < 2; nip++) {
                    unsigned bfp[4];
                    ldsm4(bfp, VtB[buf] + noff[nip] + kbb);
                    mma_f16(oc[2 * nip],     af[0], af[1], af[2], af[3], bfp[0], bfp[1]);
                    mma_f16(oc[2 * nip + 1], af[0], af[1], af[2], af[3], bfp[2], bfp[3]);
                }
            }
        }

        buf ^= 1;
    }

    // ---- epilogue: combine partner column-half row sums, normalize ----
    l0 += __shfl_xor_sync(0xffffffffu, l0, 1);
    l0 += __shfl_xor_sync(0xffffffffu, l0, 2);
    l1 += __shfl_xor_sync(0xffffffffu, l1, 1);
    l1 += __shfl_xor_sync(0xffffffffu, l1, 2);
    lred[warp * 16 + lr]     = l0;
    lred[warp * 16 + 8 + lr] = l1;
    __syncthreads();
    const int pw = warp ^ 1;
    float inv0 = 1.0f / (l0 + lred[pw * 16 + lr]);
    float inv1 = 1.0f / (l1 + lred[pw * 16 + 8 + lr]);

    int ra = q0 + r0 + lr;
#pragma unroll
    for (int ni = 0; ni < 4; ni++) {
        int col = h * D_HEAD + c0 + ni * 8 + 2 * lc;
        *(float2*)&out[((size_t)(b * S_LEN) + ra) * E_DIM + col] =
            make_float2(oc[ni][0] * inv0, oc[ni][1] * inv0);
        *(float2*)&out[((size_t)(b * S_LEN) + ra + 8) * E_DIM + col] =
            make_float2(oc[ni][2] * inv1, oc[ni][3] * inv1);
    }
}

// ---------------------------------------------------------------------------
extern "C" void kernel_launch(void* const* d_in, const int* in_sizes, int n_in,
                              void* d_out, int out_size)
{
    const float* x  = (const float*)d_in[0];
    const float* Wq = (const float*)d_in[1];
    const float* Wk = (const float*)d_in[2];
    const float* Wv = (const float*)d_in[3];
    const float* g  = (const float*)d_in[4];
    float* out = (float*)d_out;

    // 0) fp32 -> fp16 conversion of all GEMM inputs (single launch)
    cvt_all<<<(NCVT + 255) / 256, 256>>>(x, Wq, Wk, Wv);

    // 1) QKV projections (fp16 MMA + ldmatrix, fp16 outputs)
    {
        size_t smem = (size_t)4 * ASH * sizeof(__half);    // 40960
        cudaFuncSetAttribute(qkv_gemm, cudaFuncAttributeMaxDynamicSharedMemorySize,
                             (int)smem);
        dim3 grid(E_DIM / 128, M_TOT / 128, 3);
        qkv_gemm<<<grid, 256, smem>>>();
    }

    // 2) per-head L2 norm -> fp16 Q/K (g folded into Q)
    {
        const int chunks = M_TOT * H_NUM;
        dim3 ngrid(chunks / 8, 2);
        norm_heads<<<ngrid, 256>>>(g);
    }

    // 3) V transpose (fp16 -> fp16)
    {
        dim3 tgrid(S_LEN / 32, E_DIM / 64, B_NUM);
        dim3 tblk(32, 8);
        transpose_v<<<tgrid, tblk>>>();
    }

    // 4) Flash attention (fp16 MMA + ldmatrix, 3 CTAs/SM)
    {
        cudaFuncSetAttribute(attn_kernel, cudaFuncAttributeMaxDynamicSharedMemorySize,
                             ATTN_SMEM);
        dim3 agrid(S_LEN / 64, H_NUM, B_NUM);
        attn_kernel<<<agrid, 256, ATTN_SMEM>>>(out, g);
    }
}

// round 14
// speedup vs baseline: 3.9136x; 1.0815x over previous
#include <cuda_runtime.h>
#include <cuda_fp16.h>
#include <math.h>

#define S_LEN  2048
#define E_DIM  1024
#define H_NUM  16
#define D_HEAD 64
#define B_NUM  2
#define M_TOT  (B_NUM * S_LEN)   // 4096

// ---------------- device scratch (all fp16 intermediates) ----------------
__device__ __half g_Xh[(size_t)M_TOT * E_DIM];    // fp16 x
__device__ __half g_Wqh[(size_t)E_DIM * E_DIM];
__device__ __half g_Wkh[(size_t)E_DIM * E_DIM];
__device__ __half g_Wvh[(size_t)E_DIM * E_DIM];
__device__ __half g_Qr[(size_t)M_TOT * E_DIM];    // raw fp16 projections
__device__ __half g_Kr[(size_t)M_TOT * E_DIM];
__device__ __half g_Vh[(size_t)M_TOT * E_DIM];
__device__ __half g_Qh[(size_t)M_TOT * E_DIM];    // normalized fp16 Q (g folded)
__device__ __half g_Kh[(size_t)M_TOT * E_DIM];    // normalized fp16 K
__device__ __half g_Vt[(size_t)B_NUM * E_DIM * S_LEN]; // V^T: [(b*16+h)*64+d][s]

// ---------------- helpers ----------------
__device__ __forceinline__ void mma_f16(float c[4],
                                        unsigned a0, unsigned a1, unsigned a2, unsigned a3,
                                        unsigned b0, unsigned b1) {
    asm volatile(
        "mma.sync.aligned.m16n8k16.row.col.f32.f16.f16.f32 "
        "{%0,%1,%2,%3}, {%4,%5,%6,%7}, {%8,%9}, {%0,%1,%2,%3};"
        : "+f"(c[0]), "+f"(c[1]), "+f"(c[2]), "+f"(c[3])
        : "r"(a0), "r"(a1), "r"(a2), "r"(a3), "r"(b0), "r"(b1));
}

__device__ __forceinline__ void ldsm4(unsigned r[4], unsigned addr) {
    asm volatile("ldmatrix.sync.aligned.m8n8.x4.shared.b16 {%0,%1,%2,%3}, [%4];"
                 : "=r"(r[0]), "=r"(r[1]), "=r"(r[2]), "=r"(r[3]) : "r"(addr));
}

__device__ __forceinline__ void cp16(void* smem_dst, const void* gmem_src) {
    unsigned s = (unsigned)__cvta_generic_to_shared(smem_dst);
    asm volatile("cp.async.cg.shared.global [%0], [%1], 16;" :: "r"(s), "l"(gmem_src));
}
#define CP_COMMIT() asm volatile("cp.async.commit_group;")
#define CP_WAIT0()  asm volatile("cp.async.wait_group 0;")

__device__ __forceinline__ unsigned pack_h2(float a, float b) {
    __half2 h = __floats2half2_rn(a, b);
    return *(unsigned*)&h;
}

// ---------------------------------------------------------------------------
// Kernel 0: one-shot fp32 -> fp16 conversion for x, Wq, Wk, Wv.
// ---------------------------------------------------------------------------
#define NX4 (M_TOT * E_DIM / 4)     // 1048576
#define NW4 (E_DIM * E_DIM / 4)     // 262144
#define NCVT (NX4 + 3 * NW4)        // 1835008

__global__ void cvt_all(const float* __restrict__ x,  const float* __restrict__ wq,
                        const float* __restrict__ wk, const float* __restrict__ wv)
{
    int i = blockIdx.x * blockDim.x + threadIdx.x;
    if (i >= NCVT) return;
    const float* src;
    __half* dst;
    int j;
    if (i < NX4)                  { src = x;  dst = g_Xh;  j = i; }
    else if (i < NX4 + NW4)       { src = wq; dst = g_Wqh; j = i - NX4; }
    else if (i < NX4 + 2 * NW4)   { src = wk; dst = g_Wkh; j = i - NX4 - NW4; }
    else                          { src = wv; dst = g_Wvh; j = i - NX4 - 2 * NW4; }
    float4 v = ((const float4*)src)[j];
    __half2* d = (__half2*)dst;
    d[2 * j]     = __floats2half2_rn(v.x, v.y);
    d[2 * j + 1] = __floats2half2_rn(v.z, v.w);
}

// ---------------------------------------------------------------------------
// Kernel 1: C = x @ W^T via m16n8k16 fp16 MMA + ldmatrix. Tile 128x128, BK=64
// (16 stages, half the syncs of BK=32). Stride 72 halfs => conflict-free.
// ---------------------------------------------------------------------------
#define ASH (128 * 72)   // halfs per tile buffer
#define QKV_SMEM ((size_t)4 * ASH * sizeof(__half))   // 73728 B

__global__ __launch_bounds__(256, 2) void qkv_gemm()
{
    extern __shared__ __half smh[];
    const unsigned smbase = (unsigned)__cvta_generic_to_shared(smh);
    const unsigned Abase[2] = { smbase,                smbase + ASH * 2 };
    const unsigned Bbase[2] = { smbase + 2 * ASH * 2,  smbase + 3 * ASH * 2 };
    __half* As[2] = { smh,           smh + ASH };
    __half* Bs[2] = { smh + 2*ASH,   smh + 3*ASH };

    const int z  = blockIdx.z;
    const __half* W = (z == 0) ? g_Wqh : (z == 1) ? g_Wkh : g_Wvh;
    __half*       C = (z == 0) ? g_Qr  : (z == 1) ? g_Kr  : g_Vh;

    const int m0   = blockIdx.y * 128;
    const int n0   = blockIdx.x * 128;
    const int t    = threadIdx.x;
    const int warp = t >> 5;
    const int lane = t & 31;
    const int wm   = warp >> 2;
    const int wn   = warp & 3;
    const int lr   = lane >> 2;
    const int lc   = lane & 3;

    const int l7 = lane & 7;
    const int jA_row = (lane >> 3) & 1;
    const int jA_col = (lane >> 4) & 1;
    const int jB_row = (lane >> 4) & 1;
    const int jB_col = (lane >> 3) & 1;

    unsigned aoff[4], boff[2];
#pragma unroll
    for (int mi = 0; mi < 4; mi++)
        aoff[mi] = ((wm * 64 + mi * 16 + jA_row * 8 + l7) * 72 + jA_col * 8) * 2;
#pragma unroll
    for (int nip = 0; nip < 2; nip++)
        boff[nip] = ((wn * 32 + nip * 16 + jB_row * 8 + l7) * 72 + jB_col * 8) * 2;

    float acc[4][4][4];
#pragma unroll
    for (int i = 0; i < 4; i++)
#pragma unroll
        for (int j = 0; j < 4; j++)
#pragma unroll
            for (int r = 0; r < 4; r++) acc[i][j][r] = 0.0f;

    auto prefetch = [&](int ks, int buf) {
        const int k0 = ks * 64;
#pragma unroll
        for (int i = 0; i < 4; i++) {
            int s   = t + i * 256;       // 0..1023
            int row = s >> 3;            // 0..127
            int c8  = s & 7;             // 8-half chunk within 64-half row
            cp16(&As[buf][row * 72 + c8 * 8], &g_Xh[(size_t)(m0 + row) * E_DIM + k0 + c8 * 8]);
            cp16(&Bs[buf][row * 72 + c8 * 8], &W   [(size_t)(n0 + row) * E_DIM + k0 + c8 * 8]);
        }
    };

    prefetch(0, 0); CP_COMMIT();
    int buf = 0;

    for (int ks = 0; ks < 16; ks++) {
        CP_WAIT0();
        __syncthreads();
        if (ks + 1 < 16) { prefetch(ks + 1, buf ^ 1); CP_COMMIT(); }

#pragma unroll
        for (int kk = 0; kk < 4; kk++) {
            const unsigned kbb = kk * 32;
            unsigned af[4][4];
#pragma unroll
            for (int mi = 0; mi < 4; mi++)
                ldsm4(af[mi], Abase[buf] + aoff[mi] + kbb);
            unsigned bfp[2][4];
#pragma unroll
            for (int nip = 0; nip < 2; nip++)
                ldsm4(bfp[nip], Bbase[buf] + boff[nip] + kbb);
#pragma unroll
            for (int mi = 0; mi < 4; mi++)
#pragma unroll
                for (int nip = 0; nip < 2; nip++) {
                    mma_f16(acc[mi][2 * nip],     af[mi][0], af[mi][1], af[mi][2], af[mi][3],
                            bfp[nip][0], bfp[nip][1]);
                    mma_f16(acc[mi][2 * nip + 1], af[mi][0], af[mi][1], af[mi][2], af[mi][3],
                            bfp[nip][2], bfp[nip][3]);
                }
        }
        buf ^= 1;
    }

#pragma unroll
    for (int mi = 0; mi < 4; mi++) {
#pragma unroll
        for (int ni = 0; ni < 4; ni++) {
            int row = m0 + wm * 64 + mi * 16 + lr;
            int col = n0 + wn * 32 + ni * 8 + 2 * lc;
            *(__half2*)&C[(size_t)row * E_DIM + col] =
                __floats2half2_rn(acc[mi][ni][0], acc[mi][ni][1]);
            *(__half2*)&C[(size_t)(row + 8) * E_DIM + col] =
                __floats2half2_rn(acc[mi][ni][2], acc[mi][ni][3]);
        }
    }
}

// ---------------------------------------------------------------------------
// Kernel 2: per-head L2 norm (fp16 in, fp32 math), fold g into Q, fp16 out.
// ---------------------------------------------------------------------------
__global__ __launch_bounds__(256) void norm_heads(const float* __restrict__ gptr)
{
    int warp = (blockIdx.x * blockDim.x + threadIdx.x) >> 5;
    int lane = threadIdx.x & 31;
    const int total = M_TOT * H_NUM;
    if (warp >= total) return;

    const __half* src = (blockIdx.y == 0) ? g_Qr : g_Kr;
    __half*       dst = (blockIdx.y == 0) ? g_Qh : g_Kh;
    float         sc  = (blockIdx.y == 0) ? *gptr : 1.0f;

    __half2 v = ((const __half2*)(src + (size_t)warp * 64))[lane];
    float2 vf = __half22float2(v);
    float ss = vf.x * vf.x + vf.y * vf.y;
#pragma unroll
    for (int m = 16; m > 0; m >>= 1) ss += __shfl_xor_sync(0xffffffffu, ss, m);
    float inv = sc / fmaxf(sqrtf(ss), 1e-12f);
    ((__half2*)(dst + (size_t)warp * 64))[lane] = __floats2half2_rn(vf.x * inv, vf.y * inv);
}

// ---------------------------------------------------------------------------
// Kernel 3: V transpose fp16->fp16: g_Vh [b*2048+s][f] -> g_Vt [(b*E+f)][s].
// ---------------------------------------------------------------------------
__global__ __launch_bounds__(256) void transpose_v()
{
    __shared__ __half tile[32][66];
    const int s0 = blockIdx.x * 32;
    const int f0 = blockIdx.y * 64;
    const int b  = blockIdx.z;
    const int tx = threadIdx.x;      // 0..31
    const int ty = threadIdx.y;      // 0..7
    const int tid = ty * 32 + tx;

#pragma unroll
    for (int j = 0; j < 4; j++) {
        int r = ty + 8 * j;
        *(__half2*)&tile[r][2 * tx] =
            *(const __half2*)&g_Vh[(size_t)(b * S_LEN + s0 + r) * E_DIM + f0 + 2 * tx];
    }
    __syncthreads();

    const int f  = tid >> 2;
    const int sp0 = (tid & 3) * 4;
#pragma unroll
    for (int k = 0; k < 4; k++) {
        int sp = sp0 + k;
        __half2 v = __halves2half2(tile[2 * sp][f], tile[2 * sp + 1][f]);
        *(__half2*)&g_Vt[(size_t)(b * E_DIM + f0 + f) * S_LEN + s0 + 2 * sp] = v;
    }
}

// ---------------------------------------------------------------------------
// Kernel 4: flash attention, fp16 MMA + ldmatrix. Br=128, Bc=64.
// Each warp owns 16 q-rows x ALL 64 s-cols => P is fully register-resident
// (QK C-frag == PV A-frag identity), ONE __syncthreads per k-tile, no P smem,
// no cross-warp row-sum exchange. Fixed max M0 (|score| <= |g|).
// ---------------------------------------------------------------------------
#define QS_H (128 * 72)                  // Q tile halfs
#define TKV  (64 * 72)                   // K/Vt tile halfs
#define ATTN_SMEM ((QS_H + 4 * TKV) * 2) // 55296 B

__global__ __launch_bounds__(256, 2) void attn_kernel(float* __restrict__ out,
                                                      const float* __restrict__ gptr)
{
    extern __shared__ __half smh[];
    const unsigned smbase = (unsigned)__cvta_generic_to_shared(smh);
    __half* Qs     = smh;
    const unsigned QsB = smbase;
    __half* Ks[2]  = { smh + QS_H,            smh + QS_H + TKV };
    const unsigned KsB[2] = { smbase + QS_H * 2,        smbase + (QS_H + TKV) * 2 };
    __half* Vts[2] = { smh + QS_H + 2 * TKV,  smh + QS_H + 3 * TKV };
    const unsigned VtB[2] = { smbase + (QS_H + 2 * TKV) * 2, smbase + (QS_H + 3 * TKV) * 2 };

    const int b     = blockIdx.z;
    const int h     = blockIdx.y;
    const int q0    = blockIdx.x * 128;
    const int t     = threadIdx.x;
    const int warp  = t >> 5;
    const int lane  = t & 31;
    const int lr    = lane >> 2;
    const int lc    = lane & 3;
    const int r0    = warp * 16;

    const int l7 = lane & 7;
    const int jA_row = (lane >> 3) & 1;
    const int jA_col = (lane >> 4) & 1;
    const int jB_row = (lane >> 4) & 1;
    const int jB_col = (lane >> 3) & 1;

    // Q A-frag base offset (warp's 16 rows)
    const unsigned aoff = ((r0 + jA_row * 8 + l7) * 72 + jA_col * 8) * 2;
    // B-frag offsets for K / Vt tiles (4 x 16-row groups cover 64 rows)
    unsigned noff[4];
#pragma unroll
    for (int np = 0; np < 4; np++)
        noff[np] = ((np * 16 + jB_row * 8 + l7) * 72 + jB_col * 8) * 2;

    const float M0 = fabsf(gptr[0]);

    const __half* Qg  = g_Qh + ((size_t)(b * S_LEN) + q0) * E_DIM + h * D_HEAD;
    const __half* Kg  = g_Kh + (size_t)(b * S_LEN) * E_DIM + h * D_HEAD;
    const __half* Vtg = g_Vt + (size_t)(b * E_DIM + h * D_HEAD) * S_LEN;

    auto prefetch = [&](int kt, int bufi) {
#pragma unroll
        for (int i = 0; i < 2; i++) {
            int s  = t + i * 256;        // 0..511
            int r  = s >> 3;             // 0..63
            int c8 = s & 7;
            cp16(&Ks[bufi][r * 72 + c8 * 8],
                 &Kg[(size_t)(kt * 64 + r) * E_DIM + c8 * 8]);
            cp16(&Vts[bufi][r * 72 + c8 * 8],
                 &Vtg[(size_t)r * S_LEN + kt * 64 + c8 * 8]);
        }
    };
    prefetch(0, 0); CP_COMMIT();

    // stage Q tile (128x64 halfs) once
#pragma unroll
    for (int i = 0; i < 4; i++) {
        int s  = t + i * 256;            // 0..1023
        int r  = s >> 3;                 // 0..127
        int c8 = s & 7;
        *(uint4*)&Qs[r * 72 + c8 * 8] = *(const uint4*)&Qg[(size_t)r * E_DIM + c8 * 8];
    }
    __syncthreads();

    unsigned qf[4][4];
#pragma unroll
    for (int kk = 0; kk < 4; kk++)
        ldsm4(qf[kk], QsB + aoff + kk * 32);

    float oc[8][4];
#pragma unroll
    for (int ni = 0; ni < 8; ni++)
#pragma unroll
        for (int r = 0; r < 4; r++) oc[ni][r] = 0.0f;
    float l0 = 0.0f, l1 = 0.0f;

    int buf = 0;
    for (int kt = 0; kt < S_LEN / 64; kt++) {
        CP_WAIT0();
        __syncthreads();               // K/V ready; all warps done with buf^1
        if (kt + 1 < S_LEN / 64) { prefetch(kt + 1, buf ^ 1); CP_COMMIT(); }

        // ---- S = Q K^T  (16 rows x 64 cols) ----
        float sv[8][4];
#pragma unroll
        for (int ni = 0; ni < 8; ni++)
#pragma unroll
            for (int r = 0; r < 4; r++) sv[ni][r] = 0.0f;

#pragma unroll
        for (int kk = 0; kk < 4; kk++) {
            const unsigned kbb = kk * 32;
#pragma unroll
            for (int np = 0; np < 4; np++) {
                unsigned bfp[4];
                ldsm4(bfp, KsB[buf] + noff[np] + kbb);
                mma_f16(sv[2 * np],     qf[kk][0], qf[kk][1], qf[kk][2], qf[kk][3],
                        bfp[0], bfp[1]);
                mma_f16(sv[2 * np + 1], qf[kk][0], qf[kk][1], qf[kk][2], qf[kk][3],
                        bfp[2], bfp[3]);
            }
        }

        // ---- P = exp(S - M0): fully register-resident (packed fp16) ----
        unsigned pk0[8], pk1[8];
#pragma unroll
        for (int ni = 0; ni < 8; ni++) {
            float p00 = __expf(sv[ni][0] - M0);
            float p01 = __expf(sv[ni][1] - M0);
            float p10 = __expf(sv[ni][2] - M0);
            float p11 = __expf(sv[ni][3] - M0);
            l0 += p00 + p01;
            l1 += p10 + p11;
            pk0[ni] = pack_h2(p00, p01);
            pk1[ni] = pack_h2(p10, p11);
        }

        // ---- O += P @ V  (A-frags from registers via C->A identity) ----
#pragma unroll
        for (int j = 0; j < 4; j++) {
            const unsigned kbb = j * 32;
            unsigned a0 = pk0[2 * j],     a1 = pk1[2 * j];
            unsigned a2 = pk0[2 * j + 1], a3 = pk1[2 * j + 1];
#pragma unroll
            for (int np = 0; np < 4; np++) {
                unsigned bfp[4];
                ldsm4(bfp, VtB[buf] + noff[np] + kbb);
                mma_f16(oc[2 * np],     a0, a1, a2, a3, bfp[0], bfp[1]);
                mma_f16(oc[2 * np + 1], a0, a1, a2, a3, bfp[2], bfp[3]);
            }
        }

        buf ^= 1;
    }

    // ---- epilogue: warp-local row sums, normalize, store ----
    l0 += __shfl_xor_sync(0xffffffffu, l0, 1);
    l0 += __shfl_xor_sync(0xffffffffu, l0, 2);
    l1 += __shfl_xor_sync(0xffffffffu, l1, 1);
    l1 += __shfl_xor_sync(0xffffffffu, l1, 2);
    float inv0 = 1.0f / l0;
    float inv1 = 1.0f / l1;

    int ra = q0 + r0 + lr;
#pragma unroll
    for (int ni = 0; ni < 8; ni++) {
        int col = h * D_HEAD + ni * 8 + 2 * lc;
        *(float2*)&out[((size_t)(b * S_LEN) + ra) * E_DIM + col] =
            make_float2(oc[ni][0] * inv0, oc[ni][1] * inv0);
        *(float2*)&out[((size_t)(b * S_LEN) + ra + 8) * E_DIM + col] =
            make_float2(oc[ni][2] * inv1, oc[ni][3] * inv1);
    }
}

// ---------------------------------------------------------------------------
extern "C" void kernel_launch(void* const* d_in, const int* in_sizes, int n_in,
                              void* d_out, int out_size)
{
    const float* x  = (const float*)d_in[0];
    const float* Wq = (const float*)d_in[1];
    const float* Wk = (const float*)d_in[2];
    const float* Wv = (const float*)d_in[3];
    const float* g  = (const float*)d_in[4];
    float* out = (float*)d_out;

    // 0) fp32 -> fp16 conversion of all GEMM inputs (single launch)
    cvt_all<<<(NCVT + 255) / 256, 256>>>(x, Wq, Wk, Wv);

    // 1) QKV projections (fp16 MMA + ldmatrix, BK=64)
    {
        cudaFuncSetAttribute(qkv_gemm, cudaFuncAttributeMaxDynamicSharedMemorySize,
                             (int)QKV_SMEM);
        dim3 grid(E_DIM / 128, M_TOT / 128, 3);
        qkv_gemm<<<grid, 256, QKV_SMEM>>>();
    }

    // 2) per-head L2 norm -> fp16 Q/K (g folded into Q)
    {
        const int chunks = M_TOT * H_NUM;
        dim3 ngrid(chunks / 8, 2);
        norm_heads<<<ngrid, 256>>>(g);
    }

    // 3) V transpose (fp16 -> fp16)
    {
        dim3 tgrid(S_LEN / 32, E_DIM / 64, B_NUM);
        dim3 tblk(32, 8);
        transpose_v<<<tgrid, tblk>>>();
    }

    // 4) Flash attention (register-resident P, 1 sync/tile)
    {
        cudaFuncSetAttribute(attn_kernel, cudaFuncAttributeMaxDynamicSharedMemorySize,
                             ATTN_SMEM);
        dim3 agrid(S_LEN / 128, H_NUM, B_NUM);
        attn_kernel<<<agrid, 256, ATTN_SMEM>>>(out, g);
    }
}